// round 9
// baseline (speedup 1.0000x reference)
#include <cuda_runtime.h>
#include <math.h>
#include <stdint.h>

#define HH 128
#define WW 128
#define CFEAT 1024
#define CMID 512
#define NA 9
#define NPIX (HH*WW)
#define NIT (NPIX*NA)          // 147456
#define MAXOUT 300
#define SBLK (NIT/1024)        // 144
#define IMG_MAX 2048.0f

// ---------------- scratch (device globals; no allocation allowed) -------------
__device__ float g_x1[NPIX*CMID];        // conv1 output (relu'd)
__device__ float g_x2[NPIX*CMID];        // conv2 output (no relu)
__device__ float g_boxes[NIT*4];         // decoded clipped boxes y1,x1,y2,x2
__device__ float g_scores[NIT];          // sigmoid scores
__device__ unsigned g_key[2][NIT];
__device__ unsigned g_val[2][NIT];
__device__ unsigned g_counts[256*SBLK];
__device__ unsigned g_offs[256*SBLK];
__device__ float g_dummy[32];

// ---------------- packed f32x2 helpers ----------------------------------------
typedef unsigned long long u64t;

__device__ __forceinline__ void unpack2(u64t v, float& lo, float& hi) {
    asm("mov.b64 {%0, %1}, %2;" : "=f"(lo), "=f"(hi) : "l"(v));
}
__device__ __forceinline__ u64t fma2(u64t a, u64t b, u64t c) {
    u64t d; asm("fma.rn.f32x2 %0, %1, %2, %3;" : "=l"(d) : "l"(a), "l"(b), "l"(c)); return d;
}

// ---------------- dummy kernel (aligns ncu capture onto conv1) -----------------
__global__ void dummy_kernel(int tag) {
    if (threadIdx.x == 0) g_dummy[tag] = (float)tag;
}

// ---------------- 3x3 conv, tiled implicit GEMM, FFMA2 w/ pre-dup A -----------
// block: 128 pixels (one image row) x 128 out-channels. 256 threads, 8x8 micro.
#define A2_STR 264   // floats per k-row of duplicated A (256 data + 8 pad)

template<int CIN, bool RELU_IN, bool RELU_OUT>
__global__ __launch_bounds__(256, 2)
void conv3x3_kernel(const float* __restrict__ in,   // [H][W][CIN]
                    const float* __restrict__ w,    // [3][3][CIN][COUT]
                    const float* __restrict__ bias, // [COUT]
                    float* __restrict__ out,        // [H][W][COUT]
                    int COUT)
{
    const int n0  = blockIdx.x * 128;
    const int y   = blockIdx.y;
    const int tid = threadIdx.x;
    const int tx  = tid & 15;       // n dir
    const int ty  = tid >> 4;       // m dir

    __shared__ float As2[16][A2_STR];   // duplicated: As2[k][2m]=As2[k][2m+1]=a(m,k)
    __shared__ float Bs[16][128];

    u64t acc2[8][4];
#pragma unroll
    for (int i = 0; i < 8; ++i)
#pragma unroll
        for (int j = 0; j < 4; ++j) acc2[i][j] = 0ull;

#pragma unroll 1
    for (int tap = 0; tap < 9; ++tap) {
        const int ky = tap / 3, kx = tap % 3;
        const int yy = y + ky - 1;
        const bool rowok = ((unsigned)yy < (unsigned)HH);
        const float* inrow = in + (size_t)yy * WW * CIN;
        const float* wtap  = w  + (size_t)tap * CIN * COUT;

#pragma unroll 1
        for (int c0 = 0; c0 < CIN; c0 += 16) {
            // load A tile -> duplicated smem [k][2m],[2m+1]
#pragma unroll
            for (int u = 0; u < 2; ++u) {
                int id = tid + u * 256;
                int m  = id >> 2;
                int k4 = (id & 3) * 4;
                int xx = m + kx - 1;
                float4 v = make_float4(0.f, 0.f, 0.f, 0.f);
                if (rowok && (unsigned)xx < (unsigned)WW) {
                    v = *(const float4*)(inrow + (size_t)xx * CIN + c0 + k4);
                    if (RELU_IN) {
                        v.x = fmaxf(v.x, 0.f); v.y = fmaxf(v.y, 0.f);
                        v.z = fmaxf(v.z, 0.f); v.w = fmaxf(v.w, 0.f);
                    }
                }
                *(float2*)&As2[k4 + 0][2 * m] = make_float2(v.x, v.x);
                *(float2*)&As2[k4 + 1][2 * m] = make_float2(v.y, v.y);
                *(float2*)&As2[k4 + 2][2 * m] = make_float2(v.z, v.z);
                *(float2*)&As2[k4 + 3][2 * m] = make_float2(v.w, v.w);
            }
            // load B tile
#pragma unroll
            for (int u = 0; u < 2; ++u) {
                int id = tid + u * 256;
                int kb = id >> 5;
                int nb = (id & 31) * 4;
                float4 v = *(const float4*)(wtap + (size_t)(c0 + kb) * COUT + n0 + nb);
                *(float4*)&Bs[kb][nb] = v;
            }
            __syncthreads();
#pragma unroll
            for (int k = 0; k < 16; ++k) {
                // A: 4 x LDS.128, each = two (a,a) pairs
                u64t a2[8];
#pragma unroll
                for (int j = 0; j < 4; ++j) {
                    float4 p = *(const float4*)&As2[k][16 * ty + 4 * j];
                    a2[2 * j + 0] = *(const u64t*)&p.x;
                    a2[2 * j + 1] = *(const u64t*)&p.z;
                }
                // B: 2 x LDS.128 = four (b,b') pairs
                u64t b2[4];
                {
                    float4 q0 = *(const float4*)&Bs[k][tx * 8 + 0];
                    float4 q1 = *(const float4*)&Bs[k][tx * 8 + 4];
                    b2[0] = *(const u64t*)&q0.x;
                    b2[1] = *(const u64t*)&q0.z;
                    b2[2] = *(const u64t*)&q1.x;
                    b2[3] = *(const u64t*)&q1.z;
                }
#pragma unroll
                for (int i = 0; i < 8; ++i)
#pragma unroll
                    for (int j = 0; j < 4; ++j)
                        acc2[i][j] = fma2(a2[i], b2[j], acc2[i][j]);
            }
            __syncthreads();
        }
    }

    float bv[8];
#pragma unroll
    for (int j = 0; j < 8; ++j) bv[j] = bias[n0 + tx * 8 + j];

#pragma unroll
    for (int i = 0; i < 8; ++i) {
        int m = ty * 8 + i;
        float* orow = out + ((size_t)(y * WW + m)) * COUT + n0 + tx * 8;
        float v[8];
#pragma unroll
        for (int j = 0; j < 4; ++j)
            unpack2(acc2[i][j], v[2 * j], v[2 * j + 1]);
#pragma unroll
        for (int j = 0; j < 8; ++j) {
            v[j] = v[j] + bv[j];
            if (RELU_OUT) v[j] = fmaxf(v[j], 0.f);
        }
        *(float4*)(orow + 0) = make_float4(v[0], v[1], v[2], v[3]);
        *(float4*)(orow + 4) = make_float4(v[4], v[5], v[6], v[7]);
    }
}

// ---------------- head: 1x1 convs + sigmoid + decode --------------------------
__global__ __launch_bounds__(256)
void head_kernel(const float* __restrict__ x2,
                 const float* __restrict__ wsc, const float* __restrict__ bsc,
                 const float* __restrict__ wbx, const float* __restrict__ bbx)
{
    const int p0  = blockIdx.x * 64;     // pixel base
    const int tid = threadIdx.x;
    const int px  = tid & 63;
    const int g   = tid >> 6;            // 0..3

    __shared__ float xs[64][65];
    __shared__ float wsm[64][46];
    __shared__ float zb[64][48];

    float acc[12];
#pragma unroll
    for (int j = 0; j < 12; ++j) acc[j] = 0.f;

#pragma unroll 1
    for (int c0 = 0; c0 < CMID; c0 += 64) {
#pragma unroll
        for (int u = 0; u < 4; ++u) {
            int id = tid + u * 256;
            int m = id >> 4;
            int kk = (id & 15) * 4;
            float4 v = *(const float4*)(x2 + (size_t)(p0 + m) * CMID + c0 + kk);
            xs[m][kk + 0] = v.x; xs[m][kk + 1] = v.y;
            xs[m][kk + 2] = v.z; xs[m][kk + 3] = v.w;
        }
        for (int i = tid; i < 64 * 45; i += 256) {
            int k = i / 45, n = i % 45;
            float v = (n < 9) ? wsc[(size_t)(c0 + k) * 9 + n]
                              : wbx[(size_t)(c0 + k) * 36 + (n - 9)];
            wsm[k][n] = v;
        }
        __syncthreads();
#pragma unroll 8
        for (int k = 0; k < 64; ++k) {
            float a = xs[px][k];
#pragma unroll
            for (int j = 0; j < 12; ++j) {
                int n = g + 4 * j;
                if (n < 45) acc[j] = fmaf(a, wsm[k][n], acc[j]);
            }
        }
        __syncthreads();
    }

#pragma unroll
    for (int j = 0; j < 12; ++j) {
        int n = g + 4 * j;
        if (n < 45) zb[px][n] = acc[j] + ((n < 9) ? bsc[n] : bbx[n - 9]);
    }
    __syncthreads();

    const float sqrt_r[3] = {sqrtf(0.5f), 1.0f, sqrtf(2.0f)};
    const float scales[3] = {128.f, 256.f, 512.f};

    for (int t = tid; t < 64 * NA; t += 256) {
        int p = t / NA, a = t % NA;
        int gp = p0 + p;
        int y = gp / WW, x = gp % WW;
        float zs = zb[p][a];
        float score = 1.0f / (1.0f + expf(-zs));
        float dy = zb[p][9 + 4 * a + 0];
        float dx = zb[p][9 + 4 * a + 1];
        float dh = zb[p][9 + 4 * a + 2];
        float dw = zb[p][9 + 4 * a + 3];
        int si = a / 3, ri = a % 3;
        float ah = scales[si] * sqrt_r[ri];
        float aw = scales[si] / sqrt_r[ri];
        float acy = (y + 0.5f) * 16.0f;
        float acx = (x + 0.5f) * 16.0f;
        float cy = acy + dy * ah;
        float cx = acx + dx * aw;
        float h = ah * expf(dh);
        float w = aw * expf(dw);
        float y1 = fminf(fmaxf(cy - 0.5f * h, 0.f), IMG_MAX);
        float x1 = fminf(fmaxf(cx - 0.5f * w, 0.f), IMG_MAX);
        float y2 = fminf(fmaxf(cy + 0.5f * h, 0.f), IMG_MAX);
        float x2c = fminf(fmaxf(cx + 0.5f * w, 0.f), IMG_MAX);
        int gi = gp * NA + a;
        *(float4*)(g_boxes + (size_t)gi * 4) = make_float4(y1, x1, y2, x2c);
        g_scores[gi] = score;
    }
}

// ---------------- radix sort (stable LSD, 4x8 bits, descending score) ---------
__global__ __launch_bounds__(1024)
void sort_init_kernel()
{
    int i = blockIdx.x * 1024 + threadIdx.x;
    unsigned fb = __float_as_uint(g_scores[i]);   // scores > 0 -> monotone bits
    g_key[0][i] = ~fb;                            // ascending sort => desc score
    g_val[0][i] = (unsigned)i;
}

__global__ __launch_bounds__(1024)
void sort_count_kernel(int src, int shift)
{
    __shared__ unsigned hist[256];
    int tid = threadIdx.x;
    if (tid < 256) hist[tid] = 0;
    __syncthreads();
    unsigned k = g_key[src][blockIdx.x * 1024 + tid];
    atomicAdd(&hist[(k >> shift) & 255u], 1u);
    __syncthreads();
    if (tid < 256) g_counts[tid * SBLK + blockIdx.x] = hist[tid];
}

__global__ __launch_bounds__(1024)
void sort_scan_kernel()
{
    __shared__ unsigned sums[1024];
    int tid = threadIdx.x;
    const int CH = (256 * SBLK) / 1024;   // 36
    unsigned local = 0;
    int base = tid * CH;
    for (int j = 0; j < CH; ++j) local += g_counts[base + j];
    sums[tid] = local;
    __syncthreads();
    for (int off = 1; off < 1024; off <<= 1) {
        unsigned v = 0;
        if (tid >= off) v = sums[tid - off];
        __syncthreads();
        if (tid >= off) sums[tid] += v;
        __syncthreads();
    }
    unsigned run = (tid == 0) ? 0u : sums[tid - 1];
    for (int j = 0; j < CH; ++j) {
        unsigned c = g_counts[base + j];
        g_offs[base + j] = run;
        run += c;
    }
}

__global__ __launch_bounds__(1024)
void sort_scatter_kernel(int src, int shift)
{
    __shared__ unsigned wc[32][256];
    int tid = threadIdx.x;
    int wrp = tid >> 5, ln = tid & 31;
    for (int i = tid; i < 32 * 256; i += 1024) ((unsigned*)wc)[i] = 0;
    __syncthreads();
    unsigned key = g_key[src][blockIdx.x * 1024 + tid];
    unsigned val = g_val[src][blockIdx.x * 1024 + tid];
    unsigned d = (key >> shift) & 255u;
    unsigned mask = __match_any_sync(0xffffffffu, d);
    int r = __popc(mask & ((1u << ln) - 1u));
    int leader = __ffs(mask) - 1;
    if (ln == leader) wc[wrp][d] = (unsigned)__popc(mask);
    __syncthreads();
    if (tid < 256) {
        unsigned run = 0;
        for (int w2 = 0; w2 < 32; ++w2) {
            unsigned c = wc[w2][tid];
            wc[w2][tid] = run;
            run += c;
        }
    }
    __syncthreads();
    unsigned pos = g_offs[d * SBLK + blockIdx.x] + wc[wrp][d] + (unsigned)r;
    int dst = src ^ 1;
    g_key[dst][pos] = key;
    g_val[dst][pos] = val;
}

// ---------------- NMS + output -------------------------------------------------
__device__ __forceinline__ float iou_f(float4 a, float areaA, float4 b, float areaB)
{
    float iy = fmaxf(0.f, fminf(a.z, b.z) - fmaxf(a.x, b.x));
    float ix = fmaxf(0.f, fminf(a.w, b.w) - fmaxf(a.y, b.y));
    float inter = iy * ix;
    return inter / (areaA + areaB - inter + 1e-9f);
}

__global__ __launch_bounds__(1024)
void nms_kernel(float* __restrict__ out, int out_size)
{
    __shared__ float4 selB[MAXOUT];
    __shared__ float  selA[MAXOUT];
    __shared__ float  selS[MAXOUT];
    __shared__ float4 candB[1024];
    __shared__ float  candS[1024];
    __shared__ unsigned char flag[1024];
    __shared__ int sh_count, sh_stop;

    int tid = threadIdx.x;
    if (tid == 0) { sh_count = 0; sh_stop = 0; }
    __syncthreads();

    for (int pos = 0; pos < NIT; pos += 1024) {
        int i = pos + tid;
        int idx = (int)g_val[0][i];
        float s = g_scores[idx];
        float4 b = *(const float4*)(g_boxes + (size_t)idx * 4);
        candB[tid] = b;
        candS[tid] = s;
        bool ok = (s >= 0.5f);
        if (ok) {
            float area = (b.z - b.x) * (b.w - b.y);
            int cnt = sh_count;
            for (int j = 0; j < cnt; ++j) {
                if (iou_f(b, area, selB[j], selA[j]) > 0.7f) { ok = false; break; }
            }
        }
        flag[tid] = ok ? 1 : 0;
        __syncthreads();

        if (tid < 32) {
            int cnt0 = sh_count;
            int cnt2 = cnt0;
            for (int j = 0; j < 1024 && cnt2 < MAXOUT; ++j) {
                if (candS[j] < 0.5f) { if (tid == 0) sh_stop = 1; break; }
                if (!flag[j]) continue;
                float4 cb = candB[j];
                float area = (cb.z - cb.x) * (cb.w - cb.y);
                bool sup = false;
                for (int q = cnt0 + tid; q < cnt2; q += 32) {
                    if (iou_f(cb, area, selB[q], selA[q]) > 0.7f) { sup = true; break; }
                }
                unsigned bal = __ballot_sync(0xffffffffu, sup);
                if (bal == 0u) {
                    if (tid == 0) {
                        selB[cnt2] = cb;
                        selA[cnt2] = area;
                        selS[cnt2] = candS[j];
                    }
                    cnt2++;
                    __syncwarp();
                }
            }
            if (tid == 0) {
                sh_count = cnt2;
                if (cnt2 >= MAXOUT) sh_stop = 1;
            }
        }
        __syncthreads();
        int stop = sh_stop;
        __syncthreads();
        if (stop) break;
    }

    int cnt = sh_count;
    // output layout: boxes[300][4], scores[300], valid[300] as float
    for (int r = tid; r < MAXOUT; r += 1024) {
        bool v = (r < cnt);
        float4 b = v ? selB[r] : make_float4(0.f, 0.f, 0.f, 0.f);
        if (4 * r + 3 < out_size) {
            out[4 * r + 0] = b.x; out[4 * r + 1] = b.y;
            out[4 * r + 2] = b.z; out[4 * r + 3] = b.w;
        }
        if (4 * MAXOUT + r < out_size)     out[4 * MAXOUT + r] = v ? selS[r] : 0.f;
        if (5 * MAXOUT + r < out_size)     out[5 * MAXOUT + r] = v ? 1.0f : 0.f;
    }
}

// ---------------- launcher -----------------------------------------------------
extern "C" void kernel_launch(void* const* d_in, const int* in_sizes, int n_in,
                              void* d_out, int out_size)
{
    const float* features = (const float*)d_in[0];
    const float* w1  = (const float*)d_in[1];
    const float* b1  = (const float*)d_in[2];
    const float* w2  = (const float*)d_in[3];
    const float* b2  = (const float*)d_in[4];
    const float* wsc = (const float*)d_in[5];
    const float* bsc = (const float*)d_in[6];
    const float* wbx = (const float*)d_in[7];
    const float* bbx = (const float*)d_in[8];
    (void)in_sizes; (void)n_in;

    float* x1 = nullptr; float* x2 = nullptr;
    cudaGetSymbolAddress((void**)&x1, g_x1);
    cudaGetSymbolAddress((void**)&x2, g_x2);

    // 3 dummy launches: shift ncu's captured launch onto conv1
    dummy_kernel<<<1, 32>>>(0);
    dummy_kernel<<<1, 32>>>(1);
    dummy_kernel<<<1, 32>>>(2);

    // conv1: relu(in) -> conv3x3 -> +b1 -> relu
    {
        dim3 grid(CMID / 128, HH);
        conv3x3_kernel<CFEAT, true, true><<<grid, 256>>>(features, w1, b1, x1, CMID);
    }
    // conv2: conv3x3 -> +b2 (no relu)
    {
        dim3 grid(CMID / 128, HH);
        conv3x3_kernel<CMID, false, false><<<grid, 256>>>(x1, w2, b2, x2, CMID);
    }
    // heads + decode
    head_kernel<<<NPIX / 64, 256>>>(x2, wsc, bsc, wbx, bbx);

    // sort (stable LSD radix, 4 passes)
    sort_init_kernel<<<SBLK, 1024>>>();
    int src = 0;
    for (int p = 0; p < 4; ++p) {
        int shift = p * 8;
        sort_count_kernel<<<SBLK, 1024>>>(src, shift);
        sort_scan_kernel<<<1, 1024>>>();
        sort_scatter_kernel<<<SBLK, 1024>>>(src, shift);
        src ^= 1;
    }
    // after 4 passes result is back in buffer 0

    // NMS + write output
    nms_kernel<<<1, 1024>>>((float*)d_out, out_size);
}

// round 13
// speedup vs baseline: 1.2507x; 1.2507x over previous
#include <cuda_runtime.h>
#include <math.h>
#include <stdint.h>

#define HH 128
#define WW 128
#define CFEAT 1024
#define CMID 512
#define NA 9
#define NPIX (HH*WW)
#define NIT (NPIX*NA)          // 147456
#define MAXOUT 300
#define SBLK (NIT/1024)        // 144
#define IMG_MAX 2048.0f

// ---------------- scratch (device globals; no allocation allowed) -------------
__device__ float g_x1[NPIX*CMID];
__device__ float g_x2[NPIX*CMID];
__device__ float g_boxes[NIT*4];
__device__ float g_scores[NIT];
__device__ unsigned g_key[2][NIT];
__device__ unsigned g_val[2][NIT];
__device__ unsigned g_counts[256*SBLK];
__device__ unsigned g_offs[256*SBLK];
__device__ float g_dummy[32];
__device__ float g_test[128];

// ---------------- packed f32x2 helpers ----------------------------------------
typedef unsigned long long u64t;

__device__ __forceinline__ void unpack2(u64t v, float& lo, float& hi) {
    asm("mov.b64 {%0, %1}, %2;" : "=f"(lo), "=f"(hi) : "l"(v));
}
__device__ __forceinline__ u64t fma2(u64t a, u64t b, u64t c) {
    u64t d; asm("fma.rn.f32x2 %0, %1, %2, %3;" : "=l"(d) : "l"(a), "l"(b), "l"(c)); return d;
}

// ---------------- dummy kernel (aligns ncu capture onto mma_test) --------------
__global__ void dummy_kernel(int tag) {
    if (threadIdx.x == 0) g_dummy[tag] = (float)tag;
}

// ---------------- MMA diagnostic ----------------------------------------------
#define TA(m, k) (float)((((m) + (k)) % 7) - 3)
#define TB(k, n) (float)(((2 * (k) + (n)) % 5) - 2)

__device__ __forceinline__ uint32_t bfbits(float f) {
    return __float_as_uint(f) & 0xFFFF0000u;   // exact for small ints
}
__device__ __forceinline__ uint32_t pk(uint32_t b0, uint32_t b1) {
    return (b0 >> 16) | b1;                    // low half = element 0
}
__device__ __forceinline__ void mma_bf16(float d[4], const uint32_t a[4],
                                         uint32_t b0, uint32_t b1)
{
    asm volatile(
        "mma.sync.aligned.m16n8k16.row.col.f32.bf16.bf16.f32 "
        "{%0,%1,%2,%3}, {%4,%5,%6,%7}, {%8,%9}, {%0,%1,%2,%3};"
        : "+f"(d[0]), "+f"(d[1]), "+f"(d[2]), "+f"(d[3])
        : "r"(a[0]), "r"(a[1]), "r"(a[2]), "r"(a[3]), "r"(b0), "r"(b1));
}

__global__ void mma_test_kernel() {
    int lane = threadIdx.x & 31;
    int g = lane >> 2, tcc = lane & 3;
    int m0 = g, m1 = g + 8;
    int k0 = 2 * tcc, k1 = 2 * tcc + 1, k2 = 2 * tcc + 8, k3 = 2 * tcc + 9;
    uint32_t a[4];
    a[0] = pk(bfbits(TA(m0, k0)), bfbits(TA(m0, k1)));
    a[1] = pk(bfbits(TA(m1, k0)), bfbits(TA(m1, k1)));
    a[2] = pk(bfbits(TA(m0, k2)), bfbits(TA(m0, k3)));
    a[3] = pk(bfbits(TA(m1, k2)), bfbits(TA(m1, k3)));
    uint32_t b0 = pk(bfbits(TB(k0, g)), bfbits(TB(k1, g)));
    uint32_t b1 = pk(bfbits(TB(k2, g)), bfbits(TB(k3, g)));
    float d[4] = {0.f, 0.f, 0.f, 0.f};
    mma_bf16(d, a, b0, b1);
    g_test[m0 * 8 + 2 * tcc]     = d[0];
    g_test[m0 * 8 + 2 * tcc + 1] = d[1];
    g_test[m1 * 8 + 2 * tcc]     = d[2];
    g_test[m1 * 8 + 2 * tcc + 1] = d[3];
}

// timing channel: ~100ms spin iff the MMA result is wrong
__global__ void mma_check_kernel() {
    if (threadIdx.x == 0) {
        float maxd = 0.f;
        for (int m = 0; m < 16; ++m)
            for (int n = 0; n < 8; ++n) {
                float ref = 0.f;
                for (int k = 0; k < 16; ++k) ref += TA(m, k) * TB(k, n);
                maxd = fmaxf(maxd, fabsf(g_test[m * 8 + n] - ref));
            }
        g_dummy[30] = maxd;
        if (maxd > 0.5f) {
            unsigned x = 12345u;
            for (int i = 0; i < 50000000; ++i) { x ^= x << 13; x ^= x >> 17; x ^= x << 5; }
            g_dummy[31] = (float)(x & 1u);
        }
    }
}

// ---------------- 3x3 conv, tiled implicit GEMM (packed f32x2) -----------------
template<int CIN, bool RELU_IN, bool RELU_OUT>
__global__ __launch_bounds__(256, 2)
void conv3x3_kernel(const float* __restrict__ in,   // [H][W][CIN]
                    const float* __restrict__ w,    // [3][3][CIN][COUT]
                    const float* __restrict__ bias, // [COUT]
                    float* __restrict__ out,        // [H][W][COUT]
                    int COUT)
{
    const int n0  = blockIdx.x * 128;
    const int y   = blockIdx.y;
    const int tid = threadIdx.x;
    const int tx  = tid & 15;
    const int ty  = tid >> 4;

    __shared__ float As[16][132];
    __shared__ float Bs[16][128];

    u64t acc2[8][4];
#pragma unroll
    for (int i = 0; i < 8; ++i)
#pragma unroll
        for (int j = 0; j < 4; ++j) acc2[i][j] = 0ull;

#pragma unroll 1
    for (int tap = 0; tap < 9; ++tap) {
        const int ky = tap / 3, kx = tap % 3;
        const int yy = y + ky - 1;
        const bool rowok = ((unsigned)yy < (unsigned)HH);
        const float* inrow = in + (size_t)yy * WW * CIN;
        const float* wtap  = w  + (size_t)tap * CIN * COUT;

#pragma unroll 1
        for (int c0 = 0; c0 < CIN; c0 += 16) {
#pragma unroll
            for (int u = 0; u < 2; ++u) {
                int id = tid + u * 256;
                int m  = id >> 2;
                int k4 = (id & 3) * 4;
                int xx = m + kx - 1;
                float4 v = make_float4(0.f, 0.f, 0.f, 0.f);
                if (rowok && (unsigned)xx < (unsigned)WW) {
                    v = *(const float4*)(inrow + (size_t)xx * CIN + c0 + k4);
                    if (RELU_IN) {
                        v.x = fmaxf(v.x, 0.f); v.y = fmaxf(v.y, 0.f);
                        v.z = fmaxf(v.z, 0.f); v.w = fmaxf(v.w, 0.f);
                    }
                }
                As[k4 + 0][m] = v.x; As[k4 + 1][m] = v.y;
                As[k4 + 2][m] = v.z; As[k4 + 3][m] = v.w;
            }
#pragma unroll
            for (int u = 0; u < 2; ++u) {
                int id = tid + u * 256;
                int kb = id >> 5;
                int nb = (id & 31) * 4;
                float4 v = *(const float4*)(wtap + (size_t)(c0 + kb) * COUT + n0 + nb);
                *(float4*)&Bs[kb][nb] = v;
            }
            __syncthreads();
#pragma unroll
            for (int k = 0; k < 16; ++k) {
                float4 a03 = *(const float4*)&As[k][ty * 8 + 0];
                float4 a47 = *(const float4*)&As[k][ty * 8 + 4];
                u64t a2[8];
                a2[0] = *(const u64t*)&a03.x; a2[0] = (a2[0] & 0xFFFFFFFFull) | (a2[0] << 32);
                // build (a,a) pairs via mov
                {
                    float av[8] = {a03.x, a03.y, a03.z, a03.w, a47.x, a47.y, a47.z, a47.w};
#pragma unroll
                    for (int i = 0; i < 8; ++i)
                        asm("mov.b64 %0, {%1, %1};" : "=l"(a2[i]) : "f"(av[i]));
                }
                const u64t* brow = (const u64t*)&Bs[k][tx * 8];
                u64t b2[4];
                b2[0] = brow[0]; b2[1] = brow[1]; b2[2] = brow[2]; b2[3] = brow[3];
#pragma unroll
                for (int i = 0; i < 8; ++i)
#pragma unroll
                    for (int j = 0; j < 4; ++j)
                        acc2[i][j] = fma2(a2[i], b2[j], acc2[i][j]);
            }
            __syncthreads();
        }
    }

    float bv[8];
#pragma unroll
    for (int j = 0; j < 8; ++j) bv[j] = bias[n0 + tx * 8 + j];

#pragma unroll
    for (int i = 0; i < 8; ++i) {
        int m = ty * 8 + i;
        float* orow = out + ((size_t)(y * WW + m)) * COUT + n0 + tx * 8;
        float v[8];
#pragma unroll
        for (int j = 0; j < 4; ++j)
            unpack2(acc2[i][j], v[2 * j], v[2 * j + 1]);
#pragma unroll
        for (int j = 0; j < 8; ++j) {
            v[j] = v[j] + bv[j];
            if (RELU_OUT) v[j] = fmaxf(v[j], 0.f);
        }
        *(float4*)(orow + 0) = make_float4(v[0], v[1], v[2], v[3]);
        *(float4*)(orow + 4) = make_float4(v[4], v[5], v[6], v[7]);
    }
}

// ---------------- head: 1x1 convs + sigmoid + decode --------------------------
__global__ __launch_bounds__(256)
void head_kernel(const float* __restrict__ x2,
                 const float* __restrict__ wsc, const float* __restrict__ bsc,
                 const float* __restrict__ wbx, const float* __restrict__ bbx)
{
    const int p0  = blockIdx.x * 64;
    const int tid = threadIdx.x;
    const int px  = tid & 63;
    const int g   = tid >> 6;

    __shared__ float xs[64][65];
    __shared__ float wsm[64][46];
    __shared__ float zb[64][48];

    float acc[12];
#pragma unroll
    for (int j = 0; j < 12; ++j) acc[j] = 0.f;

#pragma unroll 1
    for (int c0 = 0; c0 < CMID; c0 += 64) {
#pragma unroll
        for (int u = 0; u < 4; ++u) {
            int id = tid + u * 256;
            int m = id >> 4;
            int kk = (id & 15) * 4;
            float4 v = *(const float4*)(x2 + (size_t)(p0 + m) * CMID + c0 + kk);
            xs[m][kk + 0] = v.x; xs[m][kk + 1] = v.y;
            xs[m][kk + 2] = v.z; xs[m][kk + 3] = v.w;
        }
        for (int i = tid; i < 64 * 45; i += 256) {
            int k = i / 45, n = i % 45;
            float v = (n < 9) ? wsc[(size_t)(c0 + k) * 9 + n]
                              : wbx[(size_t)(c0 + k) * 36 + (n - 9)];
            wsm[k][n] = v;
        }
        __syncthreads();
#pragma unroll 8
        for (int k = 0; k < 64; ++k) {
            float a = xs[px][k];
#pragma unroll
            for (int j = 0; j < 12; ++j) {
                int n = g + 4 * j;
                if (n < 45) acc[j] = fmaf(a, wsm[k][n], acc[j]);
            }
        }
        __syncthreads();
    }

#pragma unroll
    for (int j = 0; j < 12; ++j) {
        int n = g + 4 * j;
        if (n < 45) zb[px][n] = acc[j] + ((n < 9) ? bsc[n] : bbx[n - 9]);
    }
    __syncthreads();

    const float sqrt_r[3] = {sqrtf(0.5f), 1.0f, sqrtf(2.0f)};
    const float scales[3] = {128.f, 256.f, 512.f};

    for (int t = tid; t < 64 * NA; t += 256) {
        int p = t / NA, a = t % NA;
        int gp = p0 + p;
        int y = gp / WW, x = gp % WW;
        float zs = zb[p][a];
        float score = 1.0f / (1.0f + expf(-zs));
        float dy = zb[p][9 + 4 * a + 0];
        float dx = zb[p][9 + 4 * a + 1];
        float dh = zb[p][9 + 4 * a + 2];
        float dw = zb[p][9 + 4 * a + 3];
        int si = a / 3, ri = a % 3;
        float ah = scales[si] * sqrt_r[ri];
        float aw = scales[si] / sqrt_r[ri];
        float acy = (y + 0.5f) * 16.0f;
        float acx = (x + 0.5f) * 16.0f;
        float cy = acy + dy * ah;
        float cx = acx + dx * aw;
        float h = ah * expf(dh);
        float w = aw * expf(dw);
        float y1 = fminf(fmaxf(cy - 0.5f * h, 0.f), IMG_MAX);
        float x1 = fminf(fmaxf(cx - 0.5f * w, 0.f), IMG_MAX);
        float y2 = fminf(fmaxf(cy + 0.5f * h, 0.f), IMG_MAX);
        float x2c = fminf(fmaxf(cx + 0.5f * w, 0.f), IMG_MAX);
        int gi = gp * NA + a;
        *(float4*)(g_boxes + (size_t)gi * 4) = make_float4(y1, x1, y2, x2c);
        g_scores[gi] = score;
    }
}

// ---------------- radix sort (stable LSD, 4x8 bits, descending score) ---------
__global__ __launch_bounds__(1024)
void sort_init_kernel()
{
    int i = blockIdx.x * 1024 + threadIdx.x;
    unsigned fb = __float_as_uint(g_scores[i]);
    g_key[0][i] = ~fb;
    g_val[0][i] = (unsigned)i;
}

__global__ __launch_bounds__(1024)
void sort_count_kernel(int src, int shift)
{
    __shared__ unsigned hist[256];
    int tid = threadIdx.x;
    if (tid < 256) hist[tid] = 0;
    __syncthreads();
    unsigned k = g_key[src][blockIdx.x * 1024 + tid];
    atomicAdd(&hist[(k >> shift) & 255u], 1u);
    __syncthreads();
    if (tid < 256) g_counts[tid * SBLK + blockIdx.x] = hist[tid];
}

__global__ __launch_bounds__(1024)
void sort_scan_kernel()
{
    __shared__ unsigned sums[1024];
    int tid = threadIdx.x;
    const int CH = (256 * SBLK) / 1024;
    unsigned local = 0;
    int base = tid * CH;
    for (int j = 0; j < CH; ++j) local += g_counts[base + j];
    sums[tid] = local;
    __syncthreads();
    for (int off = 1; off < 1024; off <<= 1) {
        unsigned v = 0;
        if (tid >= off) v = sums[tid - off];
        __syncthreads();
        if (tid >= off) sums[tid] += v;
        __syncthreads();
    }
    unsigned run = (tid == 0) ? 0u : sums[tid - 1];
    for (int j = 0; j < CH; ++j) {
        unsigned c = g_counts[base + j];
        g_offs[base + j] = run;
        run += c;
    }
}

__global__ __launch_bounds__(1024)
void sort_scatter_kernel(int src, int shift)
{
    __shared__ unsigned wc[32][256];
    int tid = threadIdx.x;
    int wrp = tid >> 5, ln = tid & 31;
    for (int i = tid; i < 32 * 256; i += 1024) ((unsigned*)wc)[i] = 0;
    __syncthreads();
    unsigned key = g_key[src][blockIdx.x * 1024 + tid];
    unsigned val = g_val[src][blockIdx.x * 1024 + tid];
    unsigned d = (key >> shift) & 255u;
    unsigned mask = __match_any_sync(0xffffffffu, d);
    int r = __popc(mask & ((1u << ln) - 1u));
    int leader = __ffs(mask) - 1;
    if (ln == leader) wc[wrp][d] = (unsigned)__popc(mask);
    __syncthreads();
    if (tid < 256) {
        unsigned run = 0;
        for (int w2 = 0; w2 < 32; ++w2) {
            unsigned c = wc[w2][tid];
            wc[w2][tid] = run;
            run += c;
        }
    }
    __syncthreads();
    unsigned pos = g_offs[d * SBLK + blockIdx.x] + wc[wrp][d] + (unsigned)r;
    int dst = src ^ 1;
    g_key[dst][pos] = key;
    g_val[dst][pos] = val;
}

// ---------------- NMS + output -------------------------------------------------
__device__ __forceinline__ float iou_f(float4 a, float areaA, float4 b, float areaB)
{
    float iy = fmaxf(0.f, fminf(a.z, b.z) - fmaxf(a.x, b.x));
    float ix = fmaxf(0.f, fminf(a.w, b.w) - fmaxf(a.y, b.y));
    float inter = iy * ix;
    return inter / (areaA + areaB - inter + 1e-9f);
}

__global__ __launch_bounds__(1024)
void nms_kernel(float* __restrict__ out, int out_size)
{
    __shared__ float4 selB[MAXOUT];
    __shared__ float  selA[MAXOUT];
    __shared__ float  selS[MAXOUT];
    __shared__ float4 candB[1024];
    __shared__ float  candS[1024];
    __shared__ unsigned char flag[1024];
    __shared__ int sh_count, sh_stop;

    int tid = threadIdx.x;
    if (tid == 0) { sh_count = 0; sh_stop = 0; }
    __syncthreads();

    for (int pos = 0; pos < NIT; pos += 1024) {
        int i = pos + tid;
        int idx = (int)g_val[0][i];
        float s = g_scores[idx];
        float4 b = *(const float4*)(g_boxes + (size_t)idx * 4);
        candB[tid] = b;
        candS[tid] = s;
        bool ok = (s >= 0.5f);
        if (ok) {
            float area = (b.z - b.x) * (b.w - b.y);
            int cnt = sh_count;
            for (int j = 0; j < cnt; ++j) {
                if (iou_f(b, area, selB[j], selA[j]) > 0.7f) { ok = false; break; }
            }
        }
        flag[tid] = ok ? 1 : 0;
        __syncthreads();

        if (tid < 32) {
            int cnt0 = sh_count;
            int cnt2 = cnt0;
            for (int j = 0; j < 1024 && cnt2 < MAXOUT; ++j) {
                if (candS[j] < 0.5f) { if (tid == 0) sh_stop = 1; break; }
                if (!flag[j]) continue;
                float4 cb = candB[j];
                float area = (cb.z - cb.x) * (cb.w - cb.y);
                bool sup = false;
                for (int q = cnt0 + tid; q < cnt2; q += 32) {
                    if (iou_f(cb, area, selB[q], selA[q]) > 0.7f) { sup = true; break; }
                }
                unsigned bal = __ballot_sync(0xffffffffu, sup);
                if (bal == 0u) {
                    if (tid == 0) {
                        selB[cnt2] = cb;
                        selA[cnt2] = area;
                        selS[cnt2] = candS[j];
                    }
                    cnt2++;
                    __syncwarp();
                }
            }
            if (tid == 0) {
                sh_count = cnt2;
                if (cnt2 >= MAXOUT) sh_stop = 1;
            }
        }
        __syncthreads();
        int stop = sh_stop;
        __syncthreads();
        if (stop) break;
    }

    int cnt = sh_count;
    for (int r = tid; r < MAXOUT; r += 1024) {
        bool v = (r < cnt);
        float4 b = v ? selB[r] : make_float4(0.f, 0.f, 0.f, 0.f);
        if (4 * r + 3 < out_size) {
            out[4 * r + 0] = b.x; out[4 * r + 1] = b.y;
            out[4 * r + 2] = b.z; out[4 * r + 3] = b.w;
        }
        if (4 * MAXOUT + r < out_size)     out[4 * MAXOUT + r] = v ? selS[r] : 0.f;
        if (5 * MAXOUT + r < out_size)     out[5 * MAXOUT + r] = v ? 1.0f : 0.f;
    }
}

// ---------------- launcher -----------------------------------------------------
extern "C" void kernel_launch(void* const* d_in, const int* in_sizes, int n_in,
                              void* d_out, int out_size)
{
    const float* features = (const float*)d_in[0];
    const float* w1  = (const float*)d_in[1];
    const float* b1  = (const float*)d_in[2];
    const float* w2  = (const float*)d_in[3];
    const float* b2  = (const float*)d_in[4];
    const float* wsc = (const float*)d_in[5];
    const float* bsc = (const float*)d_in[6];
    const float* wbx = (const float*)d_in[7];
    const float* bbx = (const float*)d_in[8];
    (void)in_sizes; (void)n_in;

    float* x1 = nullptr; float* x2 = nullptr;
    cudaGetSymbolAddress((void**)&x1, g_x1);
    cudaGetSymbolAddress((void**)&x2, g_x2);

    // 3 dummies: put mma_test in the profiler's captured slot
    dummy_kernel<<<1, 32>>>(0);
    dummy_kernel<<<1, 32>>>(1);
    dummy_kernel<<<1, 32>>>(2);

    // MMA diagnostic: correct -> ~0 cost; broken -> ~100ms spin (timing channel)
    mma_test_kernel<<<1, 32>>>();
    mma_check_kernel<<<1, 32>>>();

    // conv1: relu(in) -> conv3x3 -> +b1 -> relu
    {
        dim3 grid(CMID / 128, HH);
        conv3x3_kernel<CFEAT, true, true><<<grid, 256>>>(features, w1, b1, x1, CMID);
    }
    // conv2: conv3x3 -> +b2 (no relu)
    {
        dim3 grid(CMID / 128, HH);
        conv3x3_kernel<CMID, false, false><<<grid, 256>>>(x1, w2, b2, x2, CMID);
    }
    // heads + decode
    head_kernel<<<NPIX / 64, 256>>>(x2, wsc, bsc, wbx, bbx);

    // sort (stable LSD radix, 4 passes)
    sort_init_kernel<<<SBLK, 1024>>>();
    int src = 0;
    for (int p = 0; p < 4; ++p) {
        int shift = p * 8;
        sort_count_kernel<<<SBLK, 1024>>>(src, shift);
        sort_scan_kernel<<<1, 1024>>>();
        sort_scatter_kernel<<<SBLK, 1024>>>(src, shift);
        src ^= 1;
    }

    // NMS + write output
    nms_kernel<<<1, 1024>>>((float*)d_out, out_size);
}

// round 15
// speedup vs baseline: 2.5429x; 2.0331x over previous
#include <cuda_runtime.h>
#include <math.h>
#include <stdint.h>

#define HH 128
#define WW 128
#define CFEAT 1024
#define CMID 512
#define NA 9
#define NPIX (HH*WW)
#define NIT (NPIX*NA)          // 147456
#define MAXOUT 300
#define SBLK (NIT/1024)        // 144
#define IMG_MAX 2048.0f
#define NT 4096                // 64x64 winograd tiles

// ---------------- scratch (device globals; no allocation allowed) -------------
__device__ float g_x1[NPIX*CMID];        // conv1 output
__device__ float g_x2[NPIX*CMID];        // conv2 output
__device__ float g_V[16*NT*CFEAT];       // input transform (max CIN=1024) 256MB
__device__ float g_U[16*CFEAT*CMID];     // weight transform 32MB
__device__ float g_M[16*NT*CMID];        // gemm output 128MB
__device__ float g_boxes[NIT*4];
__device__ float g_scores[NIT];
__device__ unsigned g_key[2][NIT];
__device__ unsigned g_val[2][NIT];
__device__ unsigned g_counts[256*SBLK];
__device__ unsigned g_offs[256*SBLK];
__device__ float g_dummy[32];

// ---------------- packed f32x2 helpers (proven) --------------------------------
typedef unsigned long long u64t;

__device__ __forceinline__ void unpack2(u64t v, float& lo, float& hi) {
    asm("mov.b64 {%0, %1}, %2;" : "=f"(lo), "=f"(hi) : "l"(v));
}
__device__ __forceinline__ u64t fma2(u64t a, u64t b, u64t c) {
    u64t d; asm("fma.rn.f32x2 %0, %1, %2, %3;" : "=l"(d) : "l"(a), "l"(b), "l"(c)); return d;
}

__global__ void dummy_kernel(int tag) {
    if (threadIdx.x == 0) g_dummy[tag] = (float)tag;
}

// ---------------- winograd weight transform: U = G g G^T -----------------------
template<int CIN>
__global__ __launch_bounds__(256)
void wino_wt_kernel(const float* __restrict__ w, float* __restrict__ U)
{
    int id = blockIdx.x * 256 + threadIdx.x;
    if (id >= CIN * 512) return;
    int co = id & 511;
    int ci = id >> 9;
    float g[3][3];
#pragma unroll
    for (int r = 0; r < 3; ++r)
#pragma unroll
        for (int c = 0; c < 3; ++c)
            g[r][c] = w[((size_t)(r * 3 + c) * CIN + ci) * 512 + co];
    float t[4][3];
#pragma unroll
    for (int j = 0; j < 3; ++j) {
        t[0][j] = g[0][j];
        t[1][j] = 0.5f * (g[0][j] + g[1][j] + g[2][j]);
        t[2][j] = 0.5f * (g[0][j] - g[1][j] + g[2][j]);
        t[3][j] = g[2][j];
    }
    float u[4][4];
#pragma unroll
    for (int i = 0; i < 4; ++i) {
        u[i][0] = t[i][0];
        u[i][1] = 0.5f * (t[i][0] + t[i][1] + t[i][2]);
        u[i][2] = 0.5f * (t[i][0] - t[i][1] + t[i][2]);
        u[i][3] = t[i][2];
    }
#pragma unroll
    for (int p = 0; p < 16; ++p)
        U[((size_t)p * CIN + ci) * 512 + co] = u[p >> 2][p & 3];
}

// ---------------- winograd input transform: V = B^T d B ------------------------
template<int CIN, bool RELU>
__global__ __launch_bounds__(256)
void wino_in_kernel(const float* __restrict__ in, float* __restrict__ V)
{
    const int tile = blockIdx.x;
    const int ty = tile >> 6, tx = tile & 63;
    const int y0 = 2 * ty - 1, x0 = 2 * tx - 1;

    for (int c = threadIdx.x; c < CIN; c += 256) {
        float d[4][4];
#pragma unroll
        for (int r = 0; r < 4; ++r) {
            int y = y0 + r;
            bool yok = ((unsigned)y < (unsigned)HH);
#pragma unroll
            for (int cc = 0; cc < 4; ++cc) {
                int x = x0 + cc;
                float v = 0.f;
                if (yok && (unsigned)x < (unsigned)WW) {
                    v = in[((size_t)y * WW + x) * CIN + c];
                    if (RELU) v = fmaxf(v, 0.f);
                }
                d[r][cc] = v;
            }
        }
        float w0[4][4];
#pragma unroll
        for (int j = 0; j < 4; ++j) {
            w0[0][j] = d[0][j] - d[2][j];
            w0[1][j] = d[1][j] + d[2][j];
            w0[2][j] = d[2][j] - d[1][j];
            w0[3][j] = d[1][j] - d[3][j];
        }
        float v4[4][4];
#pragma unroll
        for (int i = 0; i < 4; ++i) {
            v4[i][0] = w0[i][0] - w0[i][2];
            v4[i][1] = w0[i][1] + w0[i][2];
            v4[i][2] = w0[i][2] - w0[i][1];
            v4[i][3] = w0[i][1] - w0[i][3];
        }
#pragma unroll
        for (int p = 0; p < 16; ++p)
            V[((size_t)p * NT + tile) * CIN + c] = v4[p >> 2][p & 3];
    }
}

// ---------------- batched GEMM: M[p] = V[p] * U[p]  (proven inner loop) --------
template<int CIN>
__global__ __launch_bounds__(256, 2)
void wino_gemm_kernel(const float* __restrict__ Vg, const float* __restrict__ Ug,
                      float* __restrict__ Mg)
{
    const int n0 = blockIdx.x * 128;
    const int m0 = blockIdx.y * 128;
    const int p  = blockIdx.z;
    const float* A = Vg + (size_t)p * NT * CIN;
    const float* B = Ug + (size_t)p * CIN * 512;
    float* C = Mg + (size_t)p * NT * 512;

    const int tid = threadIdx.x;
    const int tx  = tid & 15;
    const int ty  = tid >> 4;

    __shared__ float As[16][132];
    __shared__ float Bs[16][128];

    u64t acc2[8][4];
#pragma unroll
    for (int i = 0; i < 8; ++i)
#pragma unroll
        for (int j = 0; j < 4; ++j) acc2[i][j] = 0ull;

#pragma unroll 1
    for (int c0 = 0; c0 < CIN; c0 += 16) {
#pragma unroll
        for (int u = 0; u < 2; ++u) {
            int id = tid + u * 256;
            int m  = id >> 2;
            int k4 = (id & 3) * 4;
            float4 v = *(const float4*)(A + (size_t)(m0 + m) * CIN + c0 + k4);
            As[k4 + 0][m] = v.x; As[k4 + 1][m] = v.y;
            As[k4 + 2][m] = v.z; As[k4 + 3][m] = v.w;
        }
#pragma unroll
        for (int u = 0; u < 2; ++u) {
            int id = tid + u * 256;
            int kb = id >> 5;
            int nb = (id & 31) * 4;
            float4 v = *(const float4*)(B + (size_t)(c0 + kb) * 512 + n0 + nb);
            *(float4*)&Bs[kb][nb] = v;
        }
        __syncthreads();
#pragma unroll
        for (int k = 0; k < 16; ++k) {
            float4 a03 = *(const float4*)&As[k][ty * 8 + 0];
            float4 a47 = *(const float4*)&As[k][ty * 8 + 4];
            u64t a2[8];
            {
                float av[8] = {a03.x, a03.y, a03.z, a03.w, a47.x, a47.y, a47.z, a47.w};
#pragma unroll
                for (int i = 0; i < 8; ++i)
                    asm("mov.b64 %0, {%1, %1};" : "=l"(a2[i]) : "f"(av[i]));
            }
            const u64t* brow = (const u64t*)&Bs[k][tx * 8];
            u64t b2[4];
            b2[0] = brow[0]; b2[1] = brow[1]; b2[2] = brow[2]; b2[3] = brow[3];
#pragma unroll
            for (int i = 0; i < 8; ++i)
#pragma unroll
                for (int j = 0; j < 4; ++j)
                    acc2[i][j] = fma2(a2[i], b2[j], acc2[i][j]);
        }
        __syncthreads();
    }

#pragma unroll
    for (int i = 0; i < 8; ++i) {
        int m = ty * 8 + i;
        float* crow = C + (size_t)(m0 + m) * 512 + n0 + tx * 8;
        float v[8];
#pragma unroll
        for (int j = 0; j < 4; ++j)
            unpack2(acc2[i][j], v[2 * j], v[2 * j + 1]);
        *(float4*)(crow + 0) = make_float4(v[0], v[1], v[2], v[3]);
        *(float4*)(crow + 4) = make_float4(v[4], v[5], v[6], v[7]);
    }
}

// ---------------- winograd output transform: Y = A^T m A + bias ----------------
__global__ __launch_bounds__(256)
void wino_out_kernel(const float* __restrict__ Mg, const float* __restrict__ bias,
                     float* __restrict__ out, int relu)
{
    const int tile = blockIdx.x;
    const int ty = tile >> 6, tx = tile & 63;

    for (int co = threadIdx.x; co < 512; co += 256) {
        float m[4][4];
#pragma unroll
        for (int p = 0; p < 16; ++p)
            m[p >> 2][p & 3] = Mg[((size_t)p * NT + tile) * 512 + co];
        float s[2][4];
#pragma unroll
        for (int j = 0; j < 4; ++j) {
            s[0][j] = m[0][j] + m[1][j] + m[2][j];
            s[1][j] = m[1][j] - m[2][j] - m[3][j];
        }
        float y00 = s[0][0] + s[0][1] + s[0][2];
        float y01 = s[0][1] - s[0][2] - s[0][3];
        float y10 = s[1][0] + s[1][1] + s[1][2];
        float y11 = s[1][1] - s[1][2] - s[1][3];
        float b = bias[co];
        y00 += b; y01 += b; y10 += b; y11 += b;
        if (relu) {
            y00 = fmaxf(y00, 0.f); y01 = fmaxf(y01, 0.f);
            y10 = fmaxf(y10, 0.f); y11 = fmaxf(y11, 0.f);
        }
        int oy = 2 * ty, ox = 2 * tx;
        out[((size_t)oy * WW + ox) * 512 + co]           = y00;
        out[((size_t)oy * WW + ox + 1) * 512 + co]       = y01;
        out[((size_t)(oy + 1) * WW + ox) * 512 + co]     = y10;
        out[((size_t)(oy + 1) * WW + ox + 1) * 512 + co] = y11;
    }
}

// ---------------- head: 1x1 convs + sigmoid + decode --------------------------
__global__ __launch_bounds__(256)
void head_kernel(const float* __restrict__ x2,
                 const float* __restrict__ wsc, const float* __restrict__ bsc,
                 const float* __restrict__ wbx, const float* __restrict__ bbx)
{
    const int p0  = blockIdx.x * 64;
    const int tid = threadIdx.x;
    const int px  = tid & 63;
    const int g   = tid >> 6;

    __shared__ float xs[64][65];
    __shared__ float wsm[64][46];
    __shared__ float zb[64][48];

    float acc[12];
#pragma unroll
    for (int j = 0; j < 12; ++j) acc[j] = 0.f;

#pragma unroll 1
    for (int c0 = 0; c0 < CMID; c0 += 64) {
#pragma unroll
        for (int u = 0; u < 4; ++u) {
            int id = tid + u * 256;
            int m = id >> 4;
            int kk = (id & 15) * 4;
            float4 v = *(const float4*)(x2 + (size_t)(p0 + m) * CMID + c0 + kk);
            xs[m][kk + 0] = v.x; xs[m][kk + 1] = v.y;
            xs[m][kk + 2] = v.z; xs[m][kk + 3] = v.w;
        }
        for (int i = tid; i < 64 * 45; i += 256) {
            int k = i / 45, n = i % 45;
            float v = (n < 9) ? wsc[(size_t)(c0 + k) * 9 + n]
                              : wbx[(size_t)(c0 + k) * 36 + (n - 9)];
            wsm[k][n] = v;
        }
        __syncthreads();
#pragma unroll 8
        for (int k = 0; k < 64; ++k) {
            float a = xs[px][k];
#pragma unroll
            for (int j = 0; j < 12; ++j) {
                int n = g + 4 * j;
                if (n < 45) acc[j] = fmaf(a, wsm[k][n], acc[j]);
            }
        }
        __syncthreads();
    }

#pragma unroll
    for (int j = 0; j < 12; ++j) {
        int n = g + 4 * j;
        if (n < 45) zb[px][n] = acc[j] + ((n < 9) ? bsc[n] : bbx[n - 9]);
    }
    __syncthreads();

    const float sqrt_r[3] = {sqrtf(0.5f), 1.0f, sqrtf(2.0f)};
    const float scales[3] = {128.f, 256.f, 512.f};

    for (int t = tid; t < 64 * NA; t += 256) {
        int p = t / NA, a = t % NA;
        int gp = p0 + p;
        int y = gp / WW, x = gp % WW;
        float zs = zb[p][a];
        float score = 1.0f / (1.0f + expf(-zs));
        float dy = zb[p][9 + 4 * a + 0];
        float dx = zb[p][9 + 4 * a + 1];
        float dh = zb[p][9 + 4 * a + 2];
        float dw = zb[p][9 + 4 * a + 3];
        int si = a / 3, ri = a % 3;
        float ah = scales[si] * sqrt_r[ri];
        float aw = scales[si] / sqrt_r[ri];
        float acy = (y + 0.5f) * 16.0f;
        float acx = (x + 0.5f) * 16.0f;
        float cy = acy + dy * ah;
        float cx = acx + dx * aw;
        float h = ah * expf(dh);
        float w = aw * expf(dw);
        float y1 = fminf(fmaxf(cy - 0.5f * h, 0.f), IMG_MAX);
        float x1 = fminf(fmaxf(cx - 0.5f * w, 0.f), IMG_MAX);
        float y2 = fminf(fmaxf(cy + 0.5f * h, 0.f), IMG_MAX);
        float x2c = fminf(fmaxf(cx + 0.5f * w, 0.f), IMG_MAX);
        int gi = gp * NA + a;
        *(float4*)(g_boxes + (size_t)gi * 4) = make_float4(y1, x1, y2, x2c);
        g_scores[gi] = score;
    }
}

// ---------------- radix sort (stable LSD, 4x8 bits, descending score) ---------
__global__ __launch_bounds__(1024)
void sort_init_kernel()
{
    int i = blockIdx.x * 1024 + threadIdx.x;
    unsigned fb = __float_as_uint(g_scores[i]);
    g_key[0][i] = ~fb;
    g_val[0][i] = (unsigned)i;
}

__global__ __launch_bounds__(1024)
void sort_count_kernel(int src, int shift)
{
    __shared__ unsigned hist[256];
    int tid = threadIdx.x;
    if (tid < 256) hist[tid] = 0;
    __syncthreads();
    unsigned k = g_key[src][blockIdx.x * 1024 + tid];
    atomicAdd(&hist[(k >> shift) & 255u], 1u);
    __syncthreads();
    if (tid < 256) g_counts[tid * SBLK + blockIdx.x] = hist[tid];
}

__global__ __launch_bounds__(1024)
void sort_scan_kernel()
{
    __shared__ unsigned sums[1024];
    int tid = threadIdx.x;
    const int CH = (256 * SBLK) / 1024;
    unsigned local = 0;
    int base = tid * CH;
    for (int j = 0; j < CH; ++j) local += g_counts[base + j];
    sums[tid] = local;
    __syncthreads();
    for (int off = 1; off < 1024; off <<= 1) {
        unsigned v = 0;
        if (tid >= off) v = sums[tid - off];
        __syncthreads();
        if (tid >= off) sums[tid] += v;
        __syncthreads();
    }
    unsigned run = (tid == 0) ? 0u : sums[tid - 1];
    for (int j = 0; j < CH; ++j) {
        unsigned c = g_counts[base + j];
        g_offs[base + j] = run;
        run += c;
    }
}

__global__ __launch_bounds__(1024)
void sort_scatter_kernel(int src, int shift)
{
    __shared__ unsigned wc[32][256];
    int tid = threadIdx.x;
    int wrp = tid >> 5, ln = tid & 31;
    for (int i = tid; i < 32 * 256; i += 1024) ((unsigned*)wc)[i] = 0;
    __syncthreads();
    unsigned key = g_key[src][blockIdx.x * 1024 + tid];
    unsigned val = g_val[src][blockIdx.x * 1024 + tid];
    unsigned d = (key >> shift) & 255u;
    unsigned mask = __match_any_sync(0xffffffffu, d);
    int r = __popc(mask & ((1u << ln) - 1u));
    int leader = __ffs(mask) - 1;
    if (ln == leader) wc[wrp][d] = (unsigned)__popc(mask);
    __syncthreads();
    if (tid < 256) {
        unsigned run = 0;
        for (int w2 = 0; w2 < 32; ++w2) {
            unsigned c = wc[w2][tid];
            wc[w2][tid] = run;
            run += c;
        }
    }
    __syncthreads();
    unsigned pos = g_offs[d * SBLK + blockIdx.x] + wc[wrp][d] + (unsigned)r;
    int dst = src ^ 1;
    g_key[dst][pos] = key;
    g_val[dst][pos] = val;
}

// ---------------- NMS + output -------------------------------------------------
__device__ __forceinline__ float iou_f(float4 a, float areaA, float4 b, float areaB)
{
    float iy = fmaxf(0.f, fminf(a.z, b.z) - fmaxf(a.x, b.x));
    float ix = fmaxf(0.f, fminf(a.w, b.w) - fmaxf(a.y, b.y));
    float inter = iy * ix;
    return inter / (areaA + areaB - inter + 1e-9f);
}

__global__ __launch_bounds__(1024)
void nms_kernel(float* __restrict__ out, int out_size)
{
    __shared__ float4 selB[MAXOUT];
    __shared__ float  selA[MAXOUT];
    __shared__ float  selS[MAXOUT];
    __shared__ float4 candB[1024];
    __shared__ float  candS[1024];
    __shared__ unsigned char flag[1024];
    __shared__ int sh_count, sh_stop;

    int tid = threadIdx.x;
    if (tid == 0) { sh_count = 0; sh_stop = 0; }
    __syncthreads();

    for (int pos = 0; pos < NIT; pos += 1024) {
        int i = pos + tid;
        int idx = (int)g_val[0][i];
        float s = g_scores[idx];
        float4 b = *(const float4*)(g_boxes + (size_t)idx * 4);
        candB[tid] = b;
        candS[tid] = s;
        bool ok = (s >= 0.5f);
        if (ok) {
            float area = (b.z - b.x) * (b.w - b.y);
            int cnt = sh_count;
            for (int j = 0; j < cnt; ++j) {
                if (iou_f(b, area, selB[j], selA[j]) > 0.7f) { ok = false; break; }
            }
        }
        flag[tid] = ok ? 1 : 0;
        __syncthreads();

        if (tid < 32) {
            int cnt0 = sh_count;
            int cnt2 = cnt0;
            for (int j = 0; j < 1024 && cnt2 < MAXOUT; ++j) {
                if (candS[j] < 0.5f) { if (tid == 0) sh_stop = 1; break; }
                if (!flag[j]) continue;
                float4 cb = candB[j];
                float area = (cb.z - cb.x) * (cb.w - cb.y);
                bool sup = false;
                for (int q = cnt0 + tid; q < cnt2; q += 32) {
                    if (iou_f(cb, area, selB[q], selA[q]) > 0.7f) { sup = true; break; }
                }
                unsigned bal = __ballot_sync(0xffffffffu, sup);
                if (bal == 0u) {
                    if (tid == 0) {
                        selB[cnt2] = cb;
                        selA[cnt2] = area;
                        selS[cnt2] = candS[j];
                    }
                    cnt2++;
                    __syncwarp();
                }
            }
            if (tid == 0) {
                sh_count = cnt2;
                if (cnt2 >= MAXOUT) sh_stop = 1;
            }
        }
        __syncthreads();
        int stop = sh_stop;
        __syncthreads();
        if (stop) break;
    }

    int cnt = sh_count;
    for (int r = tid; r < MAXOUT; r += 1024) {
        bool v = (r < cnt);
        float4 b = v ? selB[r] : make_float4(0.f, 0.f, 0.f, 0.f);
        if (4 * r + 3 < out_size) {
            out[4 * r + 0] = b.x; out[4 * r + 1] = b.y;
            out[4 * r + 2] = b.z; out[4 * r + 3] = b.w;
        }
        if (4 * MAXOUT + r < out_size)     out[4 * MAXOUT + r] = v ? selS[r] : 0.f;
        if (5 * MAXOUT + r < out_size)     out[5 * MAXOUT + r] = v ? 1.0f : 0.f;
    }
}

// ---------------- launcher -----------------------------------------------------
extern "C" void kernel_launch(void* const* d_in, const int* in_sizes, int n_in,
                              void* d_out, int out_size)
{
    const float* features = (const float*)d_in[0];
    const float* w1  = (const float*)d_in[1];
    const float* b1  = (const float*)d_in[2];
    const float* w2  = (const float*)d_in[3];
    const float* b2  = (const float*)d_in[4];
    const float* wsc = (const float*)d_in[5];
    const float* bsc = (const float*)d_in[6];
    const float* wbx = (const float*)d_in[7];
    const float* bbx = (const float*)d_in[8];
    (void)in_sizes; (void)n_in;

    float *x1, *x2, *V, *U, *M;
    cudaGetSymbolAddress((void**)&x1, g_x1);
    cudaGetSymbolAddress((void**)&x2, g_x2);
    cudaGetSymbolAddress((void**)&V,  g_V);
    cudaGetSymbolAddress((void**)&U,  g_U);
    cudaGetSymbolAddress((void**)&M,  g_M);

    // one dummy: aligns ncu captured slot (#3) onto conv1's GEMM
    dummy_kernel<<<1, 32>>>(0);

    // ---- conv1: winograd ----
    wino_wt_kernel<CFEAT><<<(CFEAT * 512) / 256, 256>>>(w1, U);
    wino_in_kernel<CFEAT, true><<<NT, 256>>>(features, V);
    {
        dim3 grid(512 / 128, NT / 128, 16);
        wino_gemm_kernel<CFEAT><<<grid, 256>>>(V, U, M);
    }
    wino_out_kernel<<<NT, 256>>>(M, b1, x1, 1);

    // ---- conv2: winograd ----
    wino_wt_kernel<CMID><<<(CMID * 512) / 256, 256>>>(w2, U);
    wino_in_kernel<CMID, false><<<NT, 256>>>(x1, V);
    {
        dim3 grid(512 / 128, NT / 128, 16);
        wino_gemm_kernel<CMID><<<grid, 256>>>(V, U, M);
    }
    wino_out_kernel<<<NT, 256>>>(M, b2, x2, 0);

    // heads + decode
    head_kernel<<<NPIX / 64, 256>>>(x2, wsc, bsc, wbx, bbx);

    // sort (stable LSD radix, 4 passes)
    sort_init_kernel<<<SBLK, 1024>>>();
    int src = 0;
    for (int p = 0; p < 4; ++p) {
        int shift = p * 8;
        sort_count_kernel<<<SBLK, 1024>>>(src, shift);
        sort_scan_kernel<<<1, 1024>>>();
        sort_scatter_kernel<<<SBLK, 1024>>>(src, shift);
        src ^= 1;
    }

    // NMS + write output
    nms_kernel<<<1, 1024>>>((float*)d_out, out_size);
}

// round 16
// speedup vs baseline: 3.6967x; 1.4537x over previous
#include <cuda_runtime.h>
#include <math.h>
#include <stdint.h>

#define HH 128
#define WW 128
#define CFEAT 1024
#define CMID 512
#define NA 9
#define NPIX (HH*WW)
#define NIT (NPIX*NA)          // 147456
#define MAXOUT 300
#define SBLK (NIT/1024)        // 144
#define IMG_MAX 2048.0f
#define NTT 1024               // 32x32 winograd F(4x4) tiles
#define NP 36                  // 6x6 transform positions

// ---------------- scratch (device globals; no allocation allowed) -------------
__device__ float g_x1[NPIX*CMID];
__device__ float g_x2[NPIX*CMID];
__device__ float g_V[NP*NTT*CFEAT];      // 151 MB
__device__ float g_U[NP*CFEAT*CMID];     // 75 MB
__device__ float g_M[NP*NTT*CMID];       // 75 MB
__device__ float g_boxes[NIT*4];
__device__ float g_scores[NIT];
__device__ unsigned g_key[2][NIT];
__device__ unsigned g_val[2][NIT];
__device__ unsigned g_counts[256*SBLK];
__device__ unsigned g_offs[256*SBLK];
__device__ float g_dummy[32];

// ---------------- packed f32x2 helpers (proven) --------------------------------
typedef unsigned long long u64t;

__device__ __forceinline__ void unpack2(u64t v, float& lo, float& hi) {
    asm("mov.b64 {%0, %1}, %2;" : "=f"(lo), "=f"(hi) : "l"(v));
}
__device__ __forceinline__ u64t fma2(u64t a, u64t b, u64t c) {
    u64t d; asm("fma.rn.f32x2 %0, %1, %2, %3;" : "=l"(d) : "l"(a), "l"(b), "l"(c)); return d;
}

__global__ void dummy_kernel(int tag) {
    if (threadIdx.x == 0) g_dummy[tag] = (float)tag;
}

// ---------------- F(4x4,3x3) transforms ----------------------------------------
// B^T (points 0,1,-1,2,-2,inf) applied to a 6-vector
__device__ __forceinline__ void bt6(const float x[6], float y[6]) {
    y[0] =  4.f * x[0] - 5.f * x[2] + x[4];
    y[1] = -4.f * x[1] - 4.f * x[2] + x[3] + x[4];
    y[2] =  4.f * x[1] - 4.f * x[2] - x[3] + x[4];
    y[3] = -2.f * x[1] -       x[2] + 2.f * x[3] + x[4];
    y[4] =  2.f * x[1] -       x[2] - 2.f * x[3] + x[4];
    y[5] =  4.f * x[1] - 5.f * x[3] + x[5];
}
// G applied to a 3-vector -> 6
__device__ __forceinline__ void g6(const float x[3], float y[6]) {
    const float c6 = 1.f / 6.f, c12 = 1.f / 12.f, c24 = 1.f / 24.f;
    y[0] = 0.25f * x[0];
    y[1] = -c6 * (x[0] + x[1] + x[2]);
    y[2] = -c6 * (x[0] - x[1] + x[2]);
    y[3] = c24 * x[0] + c12 * x[1] + c6 * x[2];
    y[4] = c24 * x[0] - c12 * x[1] + c6 * x[2];
    y[5] = x[2];
}
// A^T applied to a 6-vector -> 4
__device__ __forceinline__ void at6(const float x[6], float y[4]) {
    y[0] = x[0] + x[1] + x[2] + x[3] + x[4];
    y[1] = x[1] - x[2] + 2.f * x[3] - 2.f * x[4];
    y[2] = x[1] + x[2] + 4.f * x[3] + 4.f * x[4];
    y[3] = x[1] - x[2] + 8.f * x[3] - 8.f * x[4] + x[5];
}

// ---------------- weight transform: U = G g G^T --------------------------------
template<int CIN>
__global__ __launch_bounds__(256)
void wino_wt_kernel(const float* __restrict__ w, float* __restrict__ U)
{
    int id = blockIdx.x * 256 + threadIdx.x;
    if (id >= CIN * 512) return;
    int co = id & 511;
    int ci = id >> 9;
    float g[3][3];
#pragma unroll
    for (int r = 0; r < 3; ++r)
#pragma unroll
        for (int c = 0; c < 3; ++c)
            g[r][c] = w[((size_t)(r * 3 + c) * CIN + ci) * 512 + co];
    // t = G g  (6x3)
    float t[6][3];
#pragma unroll
    for (int j = 0; j < 3; ++j) {
        float col[3] = {g[0][j], g[1][j], g[2][j]};
        float out6[6];
        g6(col, out6);
#pragma unroll
        for (int i = 0; i < 6; ++i) t[i][j] = out6[i];
    }
    // u = t G^T (6x6)
#pragma unroll
    for (int i = 0; i < 6; ++i) {
        float row[3] = {t[i][0], t[i][1], t[i][2]};
        float out6[6];
        g6(row, out6);
#pragma unroll
        for (int j = 0; j < 6; ++j)
            U[((size_t)(i * 6 + j) * CIN + ci) * 512 + co] = out6[j];
    }
}

// ---------------- input transform: V = B^T d B ---------------------------------
template<int CIN, bool RELU>
__global__ __launch_bounds__(256)
void wino_in_kernel(const float* __restrict__ in, float* __restrict__ V)
{
    const int tile = blockIdx.x;
    const int ty = tile >> 5, tx = tile & 31;
    const int y0 = 4 * ty - 1, x0 = 4 * tx - 1;

    for (int c = threadIdx.x; c < CIN; c += 256) {
        float d[6][6];
#pragma unroll
        for (int r = 0; r < 6; ++r) {
            int y = y0 + r;
            bool yok = ((unsigned)y < (unsigned)HH);
#pragma unroll
            for (int cc = 0; cc < 6; ++cc) {
                int x = x0 + cc;
                float v = 0.f;
                if (yok && (unsigned)x < (unsigned)WW) {
                    v = in[((size_t)y * WW + x) * CIN + c];
                    if (RELU) v = fmaxf(v, 0.f);
                }
                d[r][cc] = v;
            }
        }
        // rows: t = B^T d
        float t[6][6];
#pragma unroll
        for (int j = 0; j < 6; ++j) {
            float col[6] = {d[0][j], d[1][j], d[2][j], d[3][j], d[4][j], d[5][j]};
            float o[6];
            bt6(col, o);
#pragma unroll
            for (int i = 0; i < 6; ++i) t[i][j] = o[i];
        }
        // cols: v = t B
#pragma unroll
        for (int i = 0; i < 6; ++i) {
            float o[6];
            bt6(t[i], o);
#pragma unroll
            for (int j = 0; j < 6; ++j)
                V[((size_t)(i * 6 + j) * NTT + tile) * CIN + c] = o[j];
        }
    }
}

// ---------------- batched GEMM: M[p] = V[p] * U[p] (proven inner loop) ---------
template<int CIN>
__global__ __launch_bounds__(256, 2)
void wino_gemm_kernel(const float* __restrict__ Vg, const float* __restrict__ Ug,
                      float* __restrict__ Mg)
{
    const int n0 = blockIdx.x * 128;
    const int m0 = blockIdx.y * 128;
    const int p  = blockIdx.z;
    const float* A = Vg + (size_t)p * NTT * CIN;
    const float* B = Ug + (size_t)p * CIN * 512;
    float* C = Mg + (size_t)p * NTT * 512;

    const int tid = threadIdx.x;
    const int tx  = tid & 15;
    const int ty  = tid >> 4;

    __shared__ float As[16][132];
    __shared__ float Bs[16][128];

    u64t acc2[8][4];
#pragma unroll
    for (int i = 0; i < 8; ++i)
#pragma unroll
        for (int j = 0; j < 4; ++j) acc2[i][j] = 0ull;

#pragma unroll 1
    for (int c0 = 0; c0 < CIN; c0 += 16) {
#pragma unroll
        for (int u = 0; u < 2; ++u) {
            int id = tid + u * 256;
            int m  = id >> 2;
            int k4 = (id & 3) * 4;
            float4 v = *(const float4*)(A + (size_t)(m0 + m) * CIN + c0 + k4);
            As[k4 + 0][m] = v.x; As[k4 + 1][m] = v.y;
            As[k4 + 2][m] = v.z; As[k4 + 3][m] = v.w;
        }
#pragma unroll
        for (int u = 0; u < 2; ++u) {
            int id = tid + u * 256;
            int kb = id >> 5;
            int nb = (id & 31) * 4;
            float4 v = *(const float4*)(B + (size_t)(c0 + kb) * 512 + n0 + nb);
            *(float4*)&Bs[kb][nb] = v;
        }
        __syncthreads();
#pragma unroll
        for (int k = 0; k < 16; ++k) {
            float4 a03 = *(const float4*)&As[k][ty * 8 + 0];
            float4 a47 = *(const float4*)&As[k][ty * 8 + 4];
            u64t a2[8];
            {
                float av[8] = {a03.x, a03.y, a03.z, a03.w, a47.x, a47.y, a47.z, a47.w};
#pragma unroll
                for (int i = 0; i < 8; ++i)
                    asm("mov.b64 %0, {%1, %1};" : "=l"(a2[i]) : "f"(av[i]));
            }
            const u64t* brow = (const u64t*)&Bs[k][tx * 8];
            u64t b2[4];
            b2[0] = brow[0]; b2[1] = brow[1]; b2[2] = brow[2]; b2[3] = brow[3];
#pragma unroll
            for (int i = 0; i < 8; ++i)
#pragma unroll
                for (int j = 0; j < 4; ++j)
                    acc2[i][j] = fma2(a2[i], b2[j], acc2[i][j]);
        }
        __syncthreads();
    }

#pragma unroll
    for (int i = 0; i < 8; ++i) {
        int m = ty * 8 + i;
        float* crow = C + (size_t)(m0 + m) * 512 + n0 + tx * 8;
        float v[8];
#pragma unroll
        for (int j = 0; j < 4; ++j)
            unpack2(acc2[i][j], v[2 * j], v[2 * j + 1]);
        *(float4*)(crow + 0) = make_float4(v[0], v[1], v[2], v[3]);
        *(float4*)(crow + 4) = make_float4(v[4], v[5], v[6], v[7]);
    }
}

// ---------------- output transform: Y = A^T m A + bias -------------------------
__global__ __launch_bounds__(256)
void wino_out_kernel(const float* __restrict__ Mg, const float* __restrict__ bias,
                     float* __restrict__ out, int relu)
{
    const int tile = blockIdx.x;
    const int ty = tile >> 5, tx = tile & 31;

    for (int co = threadIdx.x; co < 512; co += 256) {
        float m[6][6];
#pragma unroll
        for (int p = 0; p < 36; ++p)
            m[p / 6][p % 6] = Mg[((size_t)p * NTT + tile) * 512 + co];
        // rows: s = A^T m  (4x6)
        float s[4][6];
#pragma unroll
        for (int j = 0; j < 6; ++j) {
            float col[6] = {m[0][j], m[1][j], m[2][j], m[3][j], m[4][j], m[5][j]};
            float o[4];
            at6(col, o);
#pragma unroll
            for (int i = 0; i < 4; ++i) s[i][j] = o[i];
        }
        float b = bias[co];
        int oy = 4 * ty, ox = 4 * tx;
#pragma unroll
        for (int i = 0; i < 4; ++i) {
            float o[4];
            at6(s[i], o);
#pragma unroll
            for (int j = 0; j < 4; ++j) {
                float v = o[j] + b;
                if (relu) v = fmaxf(v, 0.f);
                out[((size_t)(oy + i) * WW + ox + j) * 512 + co] = v;
            }
        }
    }
}

// ---------------- head: 1x1 convs + sigmoid + decode --------------------------
__global__ __launch_bounds__(256)
void head_kernel(const float* __restrict__ x2,
                 const float* __restrict__ wsc, const float* __restrict__ bsc,
                 const float* __restrict__ wbx, const float* __restrict__ bbx)
{
    const int p0  = blockIdx.x * 64;
    const int tid = threadIdx.x;
    const int px  = tid & 63;
    const int g   = tid >> 6;

    __shared__ float xs[64][65];
    __shared__ float wsm[64][46];
    __shared__ float zb[64][48];

    float acc[12];
#pragma unroll
    for (int j = 0; j < 12; ++j) acc[j] = 0.f;

#pragma unroll 1
    for (int c0 = 0; c0 < CMID; c0 += 64) {
#pragma unroll
        for (int u = 0; u < 4; ++u) {
            int id = tid + u * 256;
            int m = id >> 4;
            int kk = (id & 15) * 4;
            float4 v = *(const float4*)(x2 + (size_t)(p0 + m) * CMID + c0 + kk);
            xs[m][kk + 0] = v.x; xs[m][kk + 1] = v.y;
            xs[m][kk + 2] = v.z; xs[m][kk + 3] = v.w;
        }
        for (int i = tid; i < 64 * 45; i += 256) {
            int k = i / 45, n = i % 45;
            float v = (n < 9) ? wsc[(size_t)(c0 + k) * 9 + n]
                              : wbx[(size_t)(c0 + k) * 36 + (n - 9)];
            wsm[k][n] = v;
        }
        __syncthreads();
#pragma unroll 8
        for (int k = 0; k < 64; ++k) {
            float a = xs[px][k];
#pragma unroll
            for (int j = 0; j < 12; ++j) {
                int n = g + 4 * j;
                if (n < 45) acc[j] = fmaf(a, wsm[k][n], acc[j]);
            }
        }
        __syncthreads();
    }

#pragma unroll
    for (int j = 0; j < 12; ++j) {
        int n = g + 4 * j;
        if (n < 45) zb[px][n] = acc[j] + ((n < 9) ? bsc[n] : bbx[n - 9]);
    }
    __syncthreads();

    const float sqrt_r[3] = {sqrtf(0.5f), 1.0f, sqrtf(2.0f)};
    const float scales[3] = {128.f, 256.f, 512.f};

    for (int t = tid; t < 64 * NA; t += 256) {
        int p = t / NA, a = t % NA;
        int gp = p0 + p;
        int y = gp / WW, x = gp % WW;
        float zs = zb[p][a];
        float score = 1.0f / (1.0f + expf(-zs));
        float dy = zb[p][9 + 4 * a + 0];
        float dx = zb[p][9 + 4 * a + 1];
        float dh = zb[p][9 + 4 * a + 2];
        float dw = zb[p][9 + 4 * a + 3];
        int si = a / 3, ri = a % 3;
        float ah = scales[si] * sqrt_r[ri];
        float aw = scales[si] / sqrt_r[ri];
        float acy = (y + 0.5f) * 16.0f;
        float acx = (x + 0.5f) * 16.0f;
        float cy = acy + dy * ah;
        float cx = acx + dx * aw;
        float h = ah * expf(dh);
        float w = aw * expf(dw);
        float y1 = fminf(fmaxf(cy - 0.5f * h, 0.f), IMG_MAX);
        float x1 = fminf(fmaxf(cx - 0.5f * w, 0.f), IMG_MAX);
        float y2 = fminf(fmaxf(cy + 0.5f * h, 0.f), IMG_MAX);
        float x2c = fminf(fmaxf(cx + 0.5f * w, 0.f), IMG_MAX);
        int gi = gp * NA + a;
        *(float4*)(g_boxes + (size_t)gi * 4) = make_float4(y1, x1, y2, x2c);
        g_scores[gi] = score;
    }
}

// ---------------- radix sort (stable LSD, 4x8 bits, descending score) ---------
__global__ __launch_bounds__(1024)
void sort_init_kernel()
{
    int i = blockIdx.x * 1024 + threadIdx.x;
    unsigned fb = __float_as_uint(g_scores[i]);
    g_key[0][i] = ~fb;
    g_val[0][i] = (unsigned)i;
}

__global__ __launch_bounds__(1024)
void sort_count_kernel(int src, int shift)
{
    __shared__ unsigned hist[256];
    int tid = threadIdx.x;
    if (tid < 256) hist[tid] = 0;
    __syncthreads();
    unsigned k = g_key[src][blockIdx.x * 1024 + tid];
    atomicAdd(&hist[(k >> shift) & 255u], 1u);
    __syncthreads();
    if (tid < 256) g_counts[tid * SBLK + blockIdx.x] = hist[tid];
}

__global__ __launch_bounds__(1024)
void sort_scan_kernel()
{
    __shared__ unsigned sums[1024];
    int tid = threadIdx.x;
    const int CH = (256 * SBLK) / 1024;
    unsigned local = 0;
    int base = tid * CH;
    for (int j = 0; j < CH; ++j) local += g_counts[base + j];
    sums[tid] = local;
    __syncthreads();
    for (int off = 1; off < 1024; off <<= 1) {
        unsigned v = 0;
        if (tid >= off) v = sums[tid - off];
        __syncthreads();
        if (tid >= off) sums[tid] += v;
        __syncthreads();
    }
    unsigned run = (tid == 0) ? 0u : sums[tid - 1];
    for (int j = 0; j < CH; ++j) {
        unsigned c = g_counts[base + j];
        g_offs[base + j] = run;
        run += c;
    }
}

__global__ __launch_bounds__(1024)
void sort_scatter_kernel(int src, int shift)
{
    __shared__ unsigned wc[32][256];
    int tid = threadIdx.x;
    int wrp = tid >> 5, ln = tid & 31;
    for (int i = tid; i < 32 * 256; i += 1024) ((unsigned*)wc)[i] = 0;
    __syncthreads();
    unsigned key = g_key[src][blockIdx.x * 1024 + tid];
    unsigned val = g_val[src][blockIdx.x * 1024 + tid];
    unsigned d = (key >> shift) & 255u;
    unsigned mask = __match_any_sync(0xffffffffu, d);
    int r = __popc(mask & ((1u << ln) - 1u));
    int leader = __ffs(mask) - 1;
    if (ln == leader) wc[wrp][d] = (unsigned)__popc(mask);
    __syncthreads();
    if (tid < 256) {
        unsigned run = 0;
        for (int w2 = 0; w2 < 32; ++w2) {
            unsigned c = wc[w2][tid];
            wc[w2][tid] = run;
            run += c;
        }
    }
    __syncthreads();
    unsigned pos = g_offs[d * SBLK + blockIdx.x] + wc[wrp][d] + (unsigned)r;
    int dst = src ^ 1;
    g_key[dst][pos] = key;
    g_val[dst][pos] = val;
}

// ---------------- NMS + output -------------------------------------------------
__device__ __forceinline__ float iou_f(float4 a, float areaA, float4 b, float areaB)
{
    float iy = fmaxf(0.f, fminf(a.z, b.z) - fmaxf(a.x, b.x));
    float ix = fmaxf(0.f, fminf(a.w, b.w) - fmaxf(a.y, b.y));
    float inter = iy * ix;
    return inter / (areaA + areaB - inter + 1e-9f);
}

__global__ __launch_bounds__(1024)
void nms_kernel(float* __restrict__ out, int out_size)
{
    __shared__ float4 selB[MAXOUT];
    __shared__ float  selA[MAXOUT];
    __shared__ float  selS[MAXOUT];
    __shared__ float4 candB[1024];
    __shared__ float  candS[1024];
    __shared__ unsigned char flag[1024];
    __shared__ int sh_count, sh_stop;

    int tid = threadIdx.x;
    if (tid == 0) { sh_count = 0; sh_stop = 0; }
    __syncthreads();

    for (int pos = 0; pos < NIT; pos += 1024) {
        int i = pos + tid;
        int idx = (int)g_val[0][i];
        float s = g_scores[idx];
        float4 b = *(const float4*)(g_boxes + (size_t)idx * 4);
        candB[tid] = b;
        candS[tid] = s;
        bool ok = (s >= 0.5f);
        if (ok) {
            float area = (b.z - b.x) * (b.w - b.y);
            int cnt = sh_count;
            for (int j = 0; j < cnt; ++j) {
                if (iou_f(b, area, selB[j], selA[j]) > 0.7f) { ok = false; break; }
            }
        }
        flag[tid] = ok ? 1 : 0;
        __syncthreads();

        if (tid < 32) {
            int cnt0 = sh_count;
            int cnt2 = cnt0;
            for (int j = 0; j < 1024 && cnt2 < MAXOUT; ++j) {
                if (candS[j] < 0.5f) { if (tid == 0) sh_stop = 1; break; }
                if (!flag[j]) continue;
                float4 cb = candB[j];
                float area = (cb.z - cb.x) * (cb.w - cb.y);
                bool sup = false;
                for (int q = cnt0 + tid; q < cnt2; q += 32) {
                    if (iou_f(cb, area, selB[q], selA[q]) > 0.7f) { sup = true; break; }
                }
                unsigned bal = __ballot_sync(0xffffffffu, sup);
                if (bal == 0u) {
                    if (tid == 0) {
                        selB[cnt2] = cb;
                        selA[cnt2] = area;
                        selS[cnt2] = candS[j];
                    }
                    cnt2++;
                    __syncwarp();
                }
            }
            if (tid == 0) {
                sh_count = cnt2;
                if (cnt2 >= MAXOUT) sh_stop = 1;
            }
        }
        __syncthreads();
        int stop = sh_stop;
        __syncthreads();
        if (stop) break;
    }

    int cnt = sh_count;
    for (int r = tid; r < MAXOUT; r += 1024) {
        bool v = (r < cnt);
        float4 b = v ? selB[r] : make_float4(0.f, 0.f, 0.f, 0.f);
        if (4 * r + 3 < out_size) {
            out[4 * r + 0] = b.x; out[4 * r + 1] = b.y;
            out[4 * r + 2] = b.z; out[4 * r + 3] = b.w;
        }
        if (4 * MAXOUT + r < out_size)     out[4 * MAXOUT + r] = v ? selS[r] : 0.f;
        if (5 * MAXOUT + r < out_size)     out[5 * MAXOUT + r] = v ? 1.0f : 0.f;
    }
}

// ---------------- launcher -----------------------------------------------------
extern "C" void kernel_launch(void* const* d_in, const int* in_sizes, int n_in,
                              void* d_out, int out_size)
{
    const float* features = (const float*)d_in[0];
    const float* w1  = (const float*)d_in[1];
    const float* b1  = (const float*)d_in[2];
    const float* w2  = (const float*)d_in[3];
    const float* b2  = (const float*)d_in[4];
    const float* wsc = (const float*)d_in[5];
    const float* bsc = (const float*)d_in[6];
    const float* wbx = (const float*)d_in[7];
    const float* bbx = (const float*)d_in[8];
    (void)in_sizes; (void)n_in;

    float *x1, *x2, *V, *U, *M;
    cudaGetSymbolAddress((void**)&x1, g_x1);
    cudaGetSymbolAddress((void**)&x2, g_x2);
    cudaGetSymbolAddress((void**)&V,  g_V);
    cudaGetSymbolAddress((void**)&U,  g_U);
    cudaGetSymbolAddress((void**)&M,  g_M);

    // one dummy: aligns ncu captured slot onto conv1's GEMM
    dummy_kernel<<<1, 32>>>(0);

    // ---- conv1: winograd F(4x4,3x3) ----
    wino_wt_kernel<CFEAT><<<(CFEAT * 512) / 256, 256>>>(w1, U);
    wino_in_kernel<CFEAT, true><<<NTT, 256>>>(features, V);
    {
        dim3 grid(512 / 128, NTT / 128, NP);
        wino_gemm_kernel<CFEAT><<<grid, 256>>>(V, U, M);
    }
    wino_out_kernel<<<NTT, 256>>>(M, b1, x1, 1);

    // ---- conv2: winograd F(4x4,3x3) ----
    wino_wt_kernel<CMID><<<(CMID * 512) / 256, 256>>>(w2, U);
    wino_in_kernel<CMID, false><<<NTT, 256>>>(x1, V);
    {
        dim3 grid(512 / 128, NTT / 128, NP);
        wino_gemm_kernel<CMID><<<grid, 256>>>(V, U, M);
    }
    wino_out_kernel<<<NTT, 256>>>(M, b2, x2, 0);

    // heads + decode
    head_kernel<<<NPIX / 64, 256>>>(x2, wsc, bsc, wbx, bbx);

    // sort (stable LSD radix, 4 passes)
    sort_init_kernel<<<SBLK, 1024>>>();
    int src = 0;
    for (int p = 0; p < 4; ++p) {
        int shift = p * 8;
        sort_count_kernel<<<SBLK, 1024>>>(src, shift);
        sort_scan_kernel<<<1, 1024>>>();
        sort_scatter_kernel<<<SBLK, 1024>>>(src, shift);
        src ^= 1;
    }

    // NMS + write output
    nms_kernel<<<1, 1024>>>((float*)d_out, out_size);
}

// round 17
// speedup vs baseline: 3.9436x; 1.0668x over previous
#include <cuda_runtime.h>
#include <math.h>
#include <stdint.h>

#define HH 128
#define WW 128
#define CFEAT 1024
#define CMID 512
#define NA 9
#define NPIX (HH*WW)
#define NIT (NPIX*NA)          // 147456
#define MAXOUT 300
#define SBLK (NIT/1024)        // 144
#define IMG_MAX 2048.0f
#define NTT 1024               // 32x32 winograd F(4x4) tiles
#define NP 36                  // 6x6 transform positions

// ---------------- scratch (device globals; no allocation allowed) -------------
__device__ float g_x1[NPIX*CMID];
__device__ float g_x2[NPIX*CMID];
__device__ float g_V[NP*NTT*CFEAT];
__device__ float g_U[NP*CFEAT*CMID];
__device__ float g_M[NP*NTT*CMID];
__device__ float g_boxes[NIT*4];
__device__ float g_scores[NIT];
__device__ unsigned g_key[2][NIT];
__device__ unsigned g_val[2][NIT];
__device__ unsigned g_counts[256*SBLK];
__device__ unsigned g_offs[256*SBLK];
__device__ float g_dummy[32];

__global__ void dummy_kernel(int tag) {
    if (threadIdx.x == 0) g_dummy[tag] = (float)tag;
}

// ---------------- F(4x4,3x3) transforms ----------------------------------------
__device__ __forceinline__ void bt6(const float x[6], float y[6]) {
    y[0] =  4.f * x[0] - 5.f * x[2] + x[4];
    y[1] = -4.f * x[1] - 4.f * x[2] + x[3] + x[4];
    y[2] =  4.f * x[1] - 4.f * x[2] - x[3] + x[4];
    y[3] = -2.f * x[1] -       x[2] + 2.f * x[3] + x[4];
    y[4] =  2.f * x[1] -       x[2] - 2.f * x[3] + x[4];
    y[5] =  4.f * x[1] - 5.f * x[3] + x[5];
}
__device__ __forceinline__ void g6(const float x[3], float y[6]) {
    const float c6 = 1.f / 6.f, c12 = 1.f / 12.f, c24 = 1.f / 24.f;
    y[0] = 0.25f * x[0];
    y[1] = -c6 * (x[0] + x[1] + x[2]);
    y[2] = -c6 * (x[0] - x[1] + x[2]);
    y[3] = c24 * x[0] + c12 * x[1] + c6 * x[2];
    y[4] = c24 * x[0] - c12 * x[1] + c6 * x[2];
    y[5] = x[2];
}
__device__ __forceinline__ void at6(const float x[6], float y[4]) {
    y[0] = x[0] + x[1] + x[2] + x[3] + x[4];
    y[1] = x[1] - x[2] + 2.f * x[3] - 2.f * x[4];
    y[2] = x[1] + x[2] + 4.f * x[3] + 4.f * x[4];
    y[3] = x[1] - x[2] + 8.f * x[3] - 8.f * x[4] + x[5];
}

// ---------------- weight transform: U = G g G^T --------------------------------
template<int CIN>
__global__ __launch_bounds__(256)
void wino_wt_kernel(const float* __restrict__ w, float* __restrict__ U)
{
    int id = blockIdx.x * 256 + threadIdx.x;
    if (id >= CIN * 512) return;
    int co = id & 511;
    int ci = id >> 9;
    float g[3][3];
#pragma unroll
    for (int r = 0; r < 3; ++r)
#pragma unroll
        for (int c = 0; c < 3; ++c)
            g[r][c] = w[((size_t)(r * 3 + c) * CIN + ci) * 512 + co];
    float t[6][3];
#pragma unroll
    for (int j = 0; j < 3; ++j) {
        float col[3] = {g[0][j], g[1][j], g[2][j]};
        float out6[6];
        g6(col, out6);
#pragma unroll
        for (int i = 0; i < 6; ++i) t[i][j] = out6[i];
    }
#pragma unroll
    for (int i = 0; i < 6; ++i) {
        float row[3] = {t[i][0], t[i][1], t[i][2]};
        float out6[6];
        g6(row, out6);
#pragma unroll
        for (int j = 0; j < 6; ++j)
            U[((size_t)(i * 6 + j) * CIN + ci) * 512 + co] = out6[j];
    }
}

// ---------------- input transform: V = B^T d B ---------------------------------
template<int CIN, bool RELU>
__global__ __launch_bounds__(256)
void wino_in_kernel(const float* __restrict__ in, float* __restrict__ V)
{
    const int tile = blockIdx.x;
    const int ty = tile >> 5, tx = tile & 31;
    const int y0 = 4 * ty - 1, x0 = 4 * tx - 1;

    for (int c = threadIdx.x; c < CIN; c += 256) {
        float d[6][6];
#pragma unroll
        for (int r = 0; r < 6; ++r) {
            int y = y0 + r;
            bool yok = ((unsigned)y < (unsigned)HH);
#pragma unroll
            for (int cc = 0; cc < 6; ++cc) {
                int x = x0 + cc;
                float v = 0.f;
                if (yok && (unsigned)x < (unsigned)WW) {
                    v = in[((size_t)y * WW + x) * CIN + c];
                    if (RELU) v = fmaxf(v, 0.f);
                }
                d[r][cc] = v;
            }
        }
        float t[6][6];
#pragma unroll
        for (int j = 0; j < 6; ++j) {
            float col[6] = {d[0][j], d[1][j], d[2][j], d[3][j], d[4][j], d[5][j]};
            float o[6];
            bt6(col, o);
#pragma unroll
            for (int i = 0; i < 6; ++i) t[i][j] = o[i];
        }
#pragma unroll
        for (int i = 0; i < 6; ++i) {
            float o[6];
            bt6(t[i], o);
#pragma unroll
            for (int j = 0; j < 6; ++j)
                V[((size_t)(i * 6 + j) * NTT + tile) * CIN + c] = o[j];
        }
    }
}

// ---------------- batched GEMM, double-buffered: M[p] = V[p] * U[p] ------------
template<int CIN>
__global__ __launch_bounds__(256, 2)
void wino_gemm_kernel(const float* __restrict__ Vg, const float* __restrict__ Ug,
                      float* __restrict__ Mg)
{
    const int n0 = blockIdx.x * 128;
    const int m0 = blockIdx.y * 128;
    const int p  = blockIdx.z;
    const float* A = Vg + (size_t)p * NTT * CIN;
    const float* B = Ug + (size_t)p * CIN * 512;
    float* C = Mg + (size_t)p * NTT * 512;

    const int tid = threadIdx.x;
    const int tx  = tid & 15;
    const int ty  = tid >> 4;

    __shared__ float As[2][16][132];
    __shared__ float Bs[2][16][128];

    // per-thread load coordinates
    const int am0 = (tid + 0)   >> 2;          // 0..63
    const int am1 = (tid + 256) >> 2;          // 64..127
    const int ak  = (tid & 3) * 4;
    const int bk0 = (tid + 0)   >> 5;          // 0..7
    const int bk1 = (tid + 256) >> 5;          // 8..15
    const int bn  = (tid & 31) * 4;

    float acc[8][8];
#pragma unroll
    for (int i = 0; i < 8; ++i)
#pragma unroll
        for (int j = 0; j < 8; ++j) acc[i][j] = 0.f;

    float4 av0, av1, bv0, bv1;

    // prologue: load first k-tile, stage into buffer 0
    av0 = *(const float4*)(A + (size_t)(m0 + am0) * CIN + ak);
    av1 = *(const float4*)(A + (size_t)(m0 + am1) * CIN + ak);
    bv0 = *(const float4*)(B + (size_t)bk0 * 512 + n0 + bn);
    bv1 = *(const float4*)(B + (size_t)bk1 * 512 + n0 + bn);
    {
        As[0][ak + 0][am0] = av0.x; As[0][ak + 1][am0] = av0.y;
        As[0][ak + 2][am0] = av0.z; As[0][ak + 3][am0] = av0.w;
        As[0][ak + 0][am1] = av1.x; As[0][ak + 1][am1] = av1.y;
        As[0][ak + 2][am1] = av1.z; As[0][ak + 3][am1] = av1.w;
        *(float4*)&Bs[0][bk0][bn] = bv0;
        *(float4*)&Bs[0][bk1][bn] = bv1;
    }
    __syncthreads();

    int buf = 0;
#pragma unroll 1
    for (int c0 = 16; c0 < CIN; c0 += 16) {
        // prefetch next k-tile from global
        av0 = *(const float4*)(A + (size_t)(m0 + am0) * CIN + c0 + ak);
        av1 = *(const float4*)(A + (size_t)(m0 + am1) * CIN + c0 + ak);
        bv0 = *(const float4*)(B + (size_t)(c0 + bk0) * 512 + n0 + bn);
        bv1 = *(const float4*)(B + (size_t)(c0 + bk1) * 512 + n0 + bn);

        // compute current buffer
#pragma unroll
        for (int k = 0; k < 16; ++k) {
            float a[8], b[8];
            *(float4*)&a[0] = *(const float4*)&As[buf][k][ty * 8 + 0];
            *(float4*)&a[4] = *(const float4*)&As[buf][k][ty * 8 + 4];
            *(float4*)&b[0] = *(const float4*)&Bs[buf][k][tx * 8 + 0];
            *(float4*)&b[4] = *(const float4*)&Bs[buf][k][tx * 8 + 4];
#pragma unroll
            for (int i = 0; i < 8; ++i)
#pragma unroll
                for (int j = 0; j < 8; ++j)
                    acc[i][j] = fmaf(a[i], b[j], acc[i][j]);
        }

        // stage prefetched tile into other buffer
        int nb = buf ^ 1;
        As[nb][ak + 0][am0] = av0.x; As[nb][ak + 1][am0] = av0.y;
        As[nb][ak + 2][am0] = av0.z; As[nb][ak + 3][am0] = av0.w;
        As[nb][ak + 0][am1] = av1.x; As[nb][ak + 1][am1] = av1.y;
        As[nb][ak + 2][am1] = av1.z; As[nb][ak + 3][am1] = av1.w;
        *(float4*)&Bs[nb][bk0][bn] = bv0;
        *(float4*)&Bs[nb][bk1][bn] = bv1;
        __syncthreads();
        buf = nb;
    }

    // last tile
#pragma unroll
    for (int k = 0; k < 16; ++k) {
        float a[8], b[8];
        *(float4*)&a[0] = *(const float4*)&As[buf][k][ty * 8 + 0];
        *(float4*)&a[4] = *(const float4*)&As[buf][k][ty * 8 + 4];
        *(float4*)&b[0] = *(const float4*)&Bs[buf][k][tx * 8 + 0];
        *(float4*)&b[4] = *(const float4*)&Bs[buf][k][tx * 8 + 4];
#pragma unroll
        for (int i = 0; i < 8; ++i)
#pragma unroll
            for (int j = 0; j < 8; ++j)
                acc[i][j] = fmaf(a[i], b[j], acc[i][j]);
    }

#pragma unroll
    for (int i = 0; i < 8; ++i) {
        int m = ty * 8 + i;
        float* crow = C + (size_t)(m0 + m) * 512 + n0 + tx * 8;
        *(float4*)(crow + 0) = make_float4(acc[i][0], acc[i][1], acc[i][2], acc[i][3]);
        *(float4*)(crow + 4) = make_float4(acc[i][4], acc[i][5], acc[i][6], acc[i][7]);
    }
}

// ---------------- output transform: Y = A^T m A + bias -------------------------
__global__ __launch_bounds__(256)
void wino_out_kernel(const float* __restrict__ Mg, const float* __restrict__ bias,
                     float* __restrict__ out, int relu)
{
    const int tile = blockIdx.x;
    const int ty = tile >> 5, tx = tile & 31;

    for (int co = threadIdx.x; co < 512; co += 256) {
        float m[6][6];
#pragma unroll
        for (int p = 0; p < 36; ++p)
            m[p / 6][p % 6] = Mg[((size_t)p * NTT + tile) * 512 + co];
        float s[4][6];
#pragma unroll
        for (int j = 0; j < 6; ++j) {
            float col[6] = {m[0][j], m[1][j], m[2][j], m[3][j], m[4][j], m[5][j]};
            float o[4];
            at6(col, o);
#pragma unroll
            for (int i = 0; i < 4; ++i) s[i][j] = o[i];
        }
        float b = bias[co];
        int oy = 4 * ty, ox = 4 * tx;
#pragma unroll
        for (int i = 0; i < 4; ++i) {
            float o[4];
            at6(s[i], o);
#pragma unroll
            for (int j = 0; j < 4; ++j) {
                float v = o[j] + b;
                if (relu) v = fmaxf(v, 0.f);
                out[((size_t)(oy + i) * WW + ox + j) * 512 + co] = v;
            }
        }
    }
}

// ---------------- head: 1x1 convs + sigmoid + decode --------------------------
__global__ __launch_bounds__(256)
void head_kernel(const float* __restrict__ x2,
                 const float* __restrict__ wsc, const float* __restrict__ bsc,
                 const float* __restrict__ wbx, const float* __restrict__ bbx)
{
    const int p0  = blockIdx.x * 64;
    const int tid = threadIdx.x;
    const int px  = tid & 63;
    const int g   = tid >> 6;

    __shared__ float xs[64][65];
    __shared__ float wsm[64][46];
    __shared__ float zb[64][48];

    float acc[12];
#pragma unroll
    for (int j = 0; j < 12; ++j) acc[j] = 0.f;

#pragma unroll 1
    for (int c0 = 0; c0 < CMID; c0 += 64) {
#pragma unroll
        for (int u = 0; u < 4; ++u) {
            int id = tid + u * 256;
            int m = id >> 4;
            int kk = (id & 15) * 4;
            float4 v = *(const float4*)(x2 + (size_t)(p0 + m) * CMID + c0 + kk);
            xs[m][kk + 0] = v.x; xs[m][kk + 1] = v.y;
            xs[m][kk + 2] = v.z; xs[m][kk + 3] = v.w;
        }
        for (int i = tid; i < 64 * 45; i += 256) {
            int k = i / 45, n = i % 45;
            float v = (n < 9) ? wsc[(size_t)(c0 + k) * 9 + n]
                              : wbx[(size_t)(c0 + k) * 36 + (n - 9)];
            wsm[k][n] = v;
        }
        __syncthreads();
#pragma unroll 8
        for (int k = 0; k < 64; ++k) {
            float a = xs[px][k];
#pragma unroll
            for (int j = 0; j < 12; ++j) {
                int n = g + 4 * j;
                if (n < 45) acc[j] = fmaf(a, wsm[k][n], acc[j]);
            }
        }
        __syncthreads();
    }

#pragma unroll
    for (int j = 0; j < 12; ++j) {
        int n = g + 4 * j;
        if (n < 45) zb[px][n] = acc[j] + ((n < 9) ? bsc[n] : bbx[n - 9]);
    }
    __syncthreads();

    const float sqrt_r[3] = {sqrtf(0.5f), 1.0f, sqrtf(2.0f)};
    const float scales[3] = {128.f, 256.f, 512.f};

    for (int t = tid; t < 64 * NA; t += 256) {
        int p = t / NA, a = t % NA;
        int gp = p0 + p;
        int y = gp / WW, x = gp % WW;
        float zs = zb[p][a];
        float score = 1.0f / (1.0f + expf(-zs));
        float dy = zb[p][9 + 4 * a + 0];
        float dx = zb[p][9 + 4 * a + 1];
        float dh = zb[p][9 + 4 * a + 2];
        float dw = zb[p][9 + 4 * a + 3];
        int si = a / 3, ri = a % 3;
        float ah = scales[si] * sqrt_r[ri];
        float aw = scales[si] / sqrt_r[ri];
        float acy = (y + 0.5f) * 16.0f;
        float acx = (x + 0.5f) * 16.0f;
        float cy = acy + dy * ah;
        float cx = acx + dx * aw;
        float h = ah * expf(dh);
        float w = aw * expf(dw);
        float y1 = fminf(fmaxf(cy - 0.5f * h, 0.f), IMG_MAX);
        float x1 = fminf(fmaxf(cx - 0.5f * w, 0.f), IMG_MAX);
        float y2 = fminf(fmaxf(cy + 0.5f * h, 0.f), IMG_MAX);
        float x2c = fminf(fmaxf(cx + 0.5f * w, 0.f), IMG_MAX);
        int gi = gp * NA + a;
        *(float4*)(g_boxes + (size_t)gi * 4) = make_float4(y1, x1, y2, x2c);
        g_scores[gi] = score;
    }
}

// ---------------- radix sort (stable LSD, 4x8 bits, descending score) ---------
__global__ __launch_bounds__(1024)
void sort_init_kernel()
{
    int i = blockIdx.x * 1024 + threadIdx.x;
    unsigned fb = __float_as_uint(g_scores[i]);
    g_key[0][i] = ~fb;
    g_val[0][i] = (unsigned)i;
}

__global__ __launch_bounds__(1024)
void sort_count_kernel(int src, int shift)
{
    __shared__ unsigned hist[256];
    int tid = threadIdx.x;
    if (tid < 256) hist[tid] = 0;
    __syncthreads();
    unsigned k = g_key[src][blockIdx.x * 1024 + tid];
    atomicAdd(&hist[(k >> shift) & 255u], 1u);
    __syncthreads();
    if (tid < 256) g_counts[tid * SBLK + blockIdx.x] = hist[tid];
}

__global__ __launch_bounds__(1024)
void sort_scan_kernel()
{
    __shared__ unsigned sums[1024];
    int tid = threadIdx.x;
    const int CH = (256 * SBLK) / 1024;
    unsigned local = 0;
    int base = tid * CH;
    for (int j = 0; j < CH; ++j) local += g_counts[base + j];
    sums[tid] = local;
    __syncthreads();
    for (int off = 1; off < 1024; off <<= 1) {
        unsigned v = 0;
        if (tid >= off) v = sums[tid - off];
        __syncthreads();
        if (tid >= off) sums[tid] += v;
        __syncthreads();
    }
    unsigned run = (tid == 0) ? 0u : sums[tid - 1];
    for (int j = 0; j < CH; ++j) {
        unsigned c = g_counts[base + j];
        g_offs[base + j] = run;
        run += c;
    }
}

__global__ __launch_bounds__(1024)
void sort_scatter_kernel(int src, int shift)
{
    __shared__ unsigned wc[32][256];
    int tid = threadIdx.x;
    int wrp = tid >> 5, ln = tid & 31;
    for (int i = tid; i < 32 * 256; i += 1024) ((unsigned*)wc)[i] = 0;
    __syncthreads();
    unsigned key = g_key[src][blockIdx.x * 1024 + tid];
    unsigned val = g_val[src][blockIdx.x * 1024 + tid];
    unsigned d = (key >> shift) & 255u;
    unsigned mask = __match_any_sync(0xffffffffu, d);
    int r = __popc(mask & ((1u << ln) - 1u));
    int leader = __ffs(mask) - 1;
    if (ln == leader) wc[wrp][d] = (unsigned)__popc(mask);
    __syncthreads();
    if (tid < 256) {
        unsigned run = 0;
        for (int w2 = 0; w2 < 32; ++w2) {
            unsigned c = wc[w2][tid];
            wc[w2][tid] = run;
            run += c;
        }
    }
    __syncthreads();
    unsigned pos = g_offs[d * SBLK + blockIdx.x] + wc[wrp][d] + (unsigned)r;
    int dst = src ^ 1;
    g_key[dst][pos] = key;
    g_val[dst][pos] = val;
}

// ---------------- NMS + output -------------------------------------------------
__device__ __forceinline__ float iou_f(float4 a, float areaA, float4 b, float areaB)
{
    float iy = fmaxf(0.f, fminf(a.z, b.z) - fmaxf(a.x, b.x));
    float ix = fmaxf(0.f, fminf(a.w, b.w) - fmaxf(a.y, b.y));
    float inter = iy * ix;
    return inter / (areaA + areaB - inter + 1e-9f);
}

__global__ __launch_bounds__(1024)
void nms_kernel(float* __restrict__ out, int out_size)
{
    __shared__ float4 selB[MAXOUT];
    __shared__ float  selA[MAXOUT];
    __shared__ float  selS[MAXOUT];
    __shared__ float4 candB[1024];
    __shared__ float  candS[1024];
    __shared__ unsigned char flag[1024];
    __shared__ int sh_count, sh_stop;

    int tid = threadIdx.x;
    if (tid == 0) { sh_count = 0; sh_stop = 0; }
    __syncthreads();

    for (int pos = 0; pos < NIT; pos += 1024) {
        int i = pos + tid;
        int idx = (int)g_val[0][i];
        float s = g_scores[idx];
        float4 b = *(const float4*)(g_boxes + (size_t)idx * 4);
        candB[tid] = b;
        candS[tid] = s;
        bool ok = (s >= 0.5f);
        if (ok) {
            float area = (b.z - b.x) * (b.w - b.y);
            int cnt = sh_count;
            for (int j = 0; j < cnt; ++j) {
                if (iou_f(b, area, selB[j], selA[j]) > 0.7f) { ok = false; break; }
            }
        }
        flag[tid] = ok ? 1 : 0;
        __syncthreads();

        if (tid < 32) {
            int cnt0 = sh_count;
            int cnt2 = cnt0;
            for (int j = 0; j < 1024 && cnt2 < MAXOUT; ++j) {
                if (candS[j] < 0.5f) { if (tid == 0) sh_stop = 1; break; }
                if (!flag[j]) continue;
                float4 cb = candB[j];
                float area = (cb.z - cb.x) * (cb.w - cb.y);
                bool sup = false;
                for (int q = cnt0 + tid; q < cnt2; q += 32) {
                    if (iou_f(cb, area, selB[q], selA[q]) > 0.7f) { sup = true; break; }
                }
                unsigned bal = __ballot_sync(0xffffffffu, sup);
                if (bal == 0u) {
                    if (tid == 0) {
                        selB[cnt2] = cb;
                        selA[cnt2] = area;
                        selS[cnt2] = candS[j];
                    }
                    cnt2++;
                    __syncwarp();
                }
            }
            if (tid == 0) {
                sh_count = cnt2;
                if (cnt2 >= MAXOUT) sh_stop = 1;
            }
        }
        __syncthreads();
        int stop = sh_stop;
        __syncthreads();
        if (stop) break;
    }

    int cnt = sh_count;
    for (int r = tid; r < MAXOUT; r += 1024) {
        bool v = (r < cnt);
        float4 b = v ? selB[r] : make_float4(0.f, 0.f, 0.f, 0.f);
        if (4 * r + 3 < out_size) {
            out[4 * r + 0] = b.x; out[4 * r + 1] = b.y;
            out[4 * r + 2] = b.z; out[4 * r + 3] = b.w;
        }
        if (4 * MAXOUT + r < out_size)     out[4 * MAXOUT + r] = v ? selS[r] : 0.f;
        if (5 * MAXOUT + r < out_size)     out[5 * MAXOUT + r] = v ? 1.0f : 0.f;
    }
}

// ---------------- launcher -----------------------------------------------------
extern "C" void kernel_launch(void* const* d_in, const int* in_sizes, int n_in,
                              void* d_out, int out_size)
{
    const float* features = (const float*)d_in[0];
    const float* w1  = (const float*)d_in[1];
    const float* b1  = (const float*)d_in[2];
    const float* w2  = (const float*)d_in[3];
    const float* b2  = (const float*)d_in[4];
    const float* wsc = (const float*)d_in[5];
    const float* bsc = (const float*)d_in[6];
    const float* wbx = (const float*)d_in[7];
    const float* bbx = (const float*)d_in[8];
    (void)in_sizes; (void)n_in;

    float *x1, *x2, *V, *U, *M;
    cudaGetSymbolAddress((void**)&x1, g_x1);
    cudaGetSymbolAddress((void**)&x2, g_x2);
    cudaGetSymbolAddress((void**)&V,  g_V);
    cudaGetSymbolAddress((void**)&U,  g_U);
    cudaGetSymbolAddress((void**)&M,  g_M);

    // one dummy: aligns ncu captured slot onto conv1's GEMM
    dummy_kernel<<<1, 32>>>(0);

    // ---- conv1: winograd F(4x4,3x3) ----
    wino_wt_kernel<CFEAT><<<(CFEAT * 512) / 256, 256>>>(w1, U);
    wino_in_kernel<CFEAT, true><<<NTT, 256>>>(features, V);
    {
        dim3 grid(512 / 128, NTT / 128, NP);
        wino_gemm_kernel<CFEAT><<<grid, 256>>>(V, U, M);
    }
    wino_out_kernel<<<NTT, 256>>>(M, b1, x1, 1);

    // ---- conv2: winograd F(4x4,3x3) ----
    wino_wt_kernel<CMID><<<(CMID * 512) / 256, 256>>>(w2, U);
    wino_in_kernel<CMID, false><<<NTT, 256>>>(x1, V);
    {
        dim3 grid(512 / 128, NTT / 128, NP);
        wino_gemm_kernel<CMID><<<grid, 256>>>(V, U, M);
    }
    wino_out_kernel<<<NTT, 256>>>(M, b2, x2, 0);

    // heads + decode
    head_kernel<<<NPIX / 64, 256>>>(x2, wsc, bsc, wbx, bbx);

    // sort (stable LSD radix, 4 passes)
    sort_init_kernel<<<SBLK, 1024>>>();
    int src = 0;
    for (int p = 0; p < 4; ++p) {
        int shift = p * 8;
        sort_count_kernel<<<SBLK, 1024>>>(src, shift);
        sort_scan_kernel<<<1, 1024>>>();
        sort_scatter_kernel<<<SBLK, 1024>>>(src, shift);
        src ^= 1;
    }

    // NMS + write output
    nms_kernel<<<1, 1024>>>((float*)d_out, out_size);
}